// round 1
// baseline (speedup 1.0000x reference)
#include <cuda_runtime.h>
#include <math.h>

// Problem constants
#define N_ASSET 8192
#define DLAT    512

// GEMM tiling
#define BM 128
#define BN 128
#define BK 16
#define TM 8
#define TN 8

// ---------------------------------------------------------------------------
// Scratch (allocation-free rule: __device__ globals)
// ---------------------------------------------------------------------------
__device__ float g_q[(size_t)N_ASSET * DLAT];
__device__ float g_k[(size_t)N_ASSET * DLAT];
__device__ float g_v[(size_t)N_ASSET * DLAT];
__device__ float g_s[(size_t)N_ASSET * N_ASSET];

// ---------------------------------------------------------------------------
// NT GEMM: C[M,N] = scale * (A[M,K] @ B[N,K]^T) + bias[N]
// A row-major (ld=K), B row-major (ld=K), C row-major (ld=N)
// Requires M%128==0, N%128==0, K%16==0.
// ---------------------------------------------------------------------------
__global__ __launch_bounds__(256)
void sgemm_nt(const float* __restrict__ A, const float* __restrict__ B,
              const float* __restrict__ bias, float* __restrict__ C,
              int M, int N, int K, float scale)
{
    __shared__ float As[BK][BM];   // transposed A tile
    __shared__ float Bs[BK][BN];   // transposed B tile

    const int tid = threadIdx.x;
    const int bm  = blockIdx.y * BM;
    const int bn  = blockIdx.x * BN;
    const int tr  = (tid / 16) * TM;   // row offset of microtile in block
    const int tc  = (tid % 16) * TN;   // col offset of microtile in block

    // loader mapping: 128 rows x 16 cols = 512 float4 slots, 2 per thread
    const int lrow = tid >> 2;          // 0..63
    const int lcol = (tid & 3) << 2;    // 0,4,8,12

    const float* Ab = A + (size_t)bm * K;
    const float* Bb = B + (size_t)bn * K;

    float acc[TM][TN] = {};

    for (int k0 = 0; k0 < K; k0 += BK) {
        #pragma unroll
        for (int h = 0; h < 2; ++h) {
            int r = lrow + h * 64;
            float4 t = *reinterpret_cast<const float4*>(&Ab[(size_t)r * K + k0 + lcol]);
            As[lcol + 0][r] = t.x; As[lcol + 1][r] = t.y;
            As[lcol + 2][r] = t.z; As[lcol + 3][r] = t.w;
        }
        #pragma unroll
        for (int h = 0; h < 2; ++h) {
            int r = lrow + h * 64;
            float4 t = *reinterpret_cast<const float4*>(&Bb[(size_t)r * K + k0 + lcol]);
            Bs[lcol + 0][r] = t.x; Bs[lcol + 1][r] = t.y;
            Bs[lcol + 2][r] = t.z; Bs[lcol + 3][r] = t.w;
        }
        __syncthreads();

        #pragma unroll
        for (int kk = 0; kk < BK; ++kk) {
            float a[TM], b[TN];
            #pragma unroll
            for (int i = 0; i < TM; ++i) a[i] = As[kk][tr + i];
            #pragma unroll
            for (int j = 0; j < TN; ++j) b[j] = Bs[kk][tc + j];
            #pragma unroll
            for (int i = 0; i < TM; ++i)
                #pragma unroll
                for (int j = 0; j < TN; ++j)
                    acc[i][j] += a[i] * b[j];
        }
        __syncthreads();
    }

    float bb[TN];
    #pragma unroll
    for (int j = 0; j < TN; ++j) bb[j] = bias ? bias[bn + tc + j] : 0.0f;

    #pragma unroll
    for (int i = 0; i < TM; ++i) {
        size_t crow = (size_t)(bm + tr + i) * N + bn + tc;
        #pragma unroll
        for (int j = 0; j < TN; ++j)
            C[crow + j] = acc[i][j] * scale + bb[j];
    }
}

// ---------------------------------------------------------------------------
// NN GEMM: C[M,N] = A[M,K] @ B[K,N]
// A row-major (ld=K), B row-major (ld=N), C row-major (ld=N)
// ---------------------------------------------------------------------------
__global__ __launch_bounds__(256)
void sgemm_nn(const float* __restrict__ A, const float* __restrict__ B,
              float* __restrict__ C, int M, int N, int K)
{
    __shared__ float As[BK][BM];
    __shared__ float Bs[BK][BN];

    const int tid = threadIdx.x;
    const int bm  = blockIdx.y * BM;
    const int bn  = blockIdx.x * BN;
    const int tr  = (tid / 16) * TM;
    const int tc  = (tid % 16) * TN;

    const int lrow = tid >> 2;          // A loader: 0..63
    const int lcol = (tid & 3) << 2;    // 0,4,8,12

    const float* Ab = A + (size_t)bm * K;

    float acc[TM][TN] = {};

    for (int k0 = 0; k0 < K; k0 += BK) {
        #pragma unroll
        for (int h = 0; h < 2; ++h) {
            int r = lrow + h * 64;
            float4 t = *reinterpret_cast<const float4*>(&Ab[(size_t)r * K + k0 + lcol]);
            As[lcol + 0][r] = t.x; As[lcol + 1][r] = t.y;
            As[lcol + 2][r] = t.z; As[lcol + 3][r] = t.w;
        }
        // B tile: rows k0..k0+15, cols bn..bn+127 (fully coalesced)
        #pragma unroll
        for (int h = 0; h < 2; ++h) {
            int slot = tid + h * 256;        // 0..511
            int br   = slot >> 5;            // 0..15
            int bc   = (slot & 31) << 2;     // 0..124
            float4 t = *reinterpret_cast<const float4*>(&B[(size_t)(k0 + br) * N + bn + bc]);
            *reinterpret_cast<float4*>(&Bs[br][bc]) = t;
        }
        __syncthreads();

        #pragma unroll
        for (int kk = 0; kk < BK; ++kk) {
            float a[TM], b[TN];
            #pragma unroll
            for (int i = 0; i < TM; ++i) a[i] = As[kk][tr + i];
            #pragma unroll
            for (int j = 0; j < TN; ++j) b[j] = Bs[kk][tc + j];
            #pragma unroll
            for (int i = 0; i < TM; ++i)
                #pragma unroll
                for (int j = 0; j < TN; ++j)
                    acc[i][j] += a[i] * b[j];
        }
        __syncthreads();
    }

    #pragma unroll
    for (int i = 0; i < TM; ++i) {
        size_t crow = (size_t)(bm + tr + i) * N + bn + tc;
        #pragma unroll
        for (int j = 0; j < TN; ++j)
            C[crow + j] = acc[i][j];
    }
}

// ---------------------------------------------------------------------------
// Row softmax: one block per row of 8192, values held in registers (32/thread)
// ---------------------------------------------------------------------------
__global__ __launch_bounds__(256)
void softmax_rows(float* __restrict__ S, int N)
{
    const int tid = threadIdx.x;
    float* s = S + (size_t)blockIdx.x * N;

    float v[32];
    float m = -3.4e38f;
    #pragma unroll
    for (int i = 0; i < 32; ++i) {
        v[i] = s[i * 256 + tid];
        m = fmaxf(m, v[i]);
    }

    __shared__ float red[8];
    __shared__ float bcast;

    // block max
    #pragma unroll
    for (int o = 16; o > 0; o >>= 1) m = fmaxf(m, __shfl_xor_sync(0xffffffffu, m, o));
    if ((tid & 31) == 0) red[tid >> 5] = m;
    __syncthreads();
    if (tid < 32) {
        float t = (tid < 8) ? red[tid] : -3.4e38f;
        #pragma unroll
        for (int o = 4; o > 0; o >>= 1) t = fmaxf(t, __shfl_xor_sync(0xffffffffu, t, o));
        if (tid == 0) bcast = t;
    }
    __syncthreads();
    m = bcast;
    __syncthreads();

    // exp + block sum
    float sum = 0.0f;
    #pragma unroll
    for (int i = 0; i < 32; ++i) {
        v[i] = __expf(v[i] - m);
        sum += v[i];
    }
    #pragma unroll
    for (int o = 16; o > 0; o >>= 1) sum += __shfl_xor_sync(0xffffffffu, sum, o);
    if ((tid & 31) == 0) red[tid >> 5] = sum;
    __syncthreads();
    if (tid < 32) {
        float t = (tid < 8) ? red[tid] : 0.0f;
        #pragma unroll
        for (int o = 4; o > 0; o >>= 1) t += __shfl_xor_sync(0xffffffffu, t, o);
        if (tid == 0) bcast = t;
    }
    __syncthreads();

    const float inv = 1.0f / bcast;
    #pragma unroll
    for (int i = 0; i < 32; ++i)
        s[i * 256 + tid] = v[i] * inv;
}

// ---------------------------------------------------------------------------
// kernel_launch
// Inputs (metadata order): z, Wq, bq, Wk, bk, Wv, bv   — all float32
// Output: h (8192 x 512) float32
// ---------------------------------------------------------------------------
extern "C" void kernel_launch(void* const* d_in, const int* in_sizes, int n_in,
                              void* d_out, int out_size)
{
    const float* z  = (const float*)d_in[0];
    const float* Wq = (const float*)d_in[1];
    const float* bq = (const float*)d_in[2];
    const float* Wk = (const float*)d_in[3];
    const float* bk = (const float*)d_in[4];
    const float* Wv = (const float*)d_in[5];
    const float* bv = (const float*)d_in[6];
    float* out = (float*)d_out;

    float *q, *k, *v, *s;
    cudaGetSymbolAddress((void**)&q, g_q);
    cudaGetSymbolAddress((void**)&k, g_k);
    cudaGetSymbolAddress((void**)&v, g_v);
    cudaGetSymbolAddress((void**)&s, g_s);

    dim3 blk(256);

    // QKV projections: [8192,512] = z @ W^T + b
    dim3 gp(DLAT / BN, N_ASSET / BM);   // 4 x 64
    sgemm_nt<<<gp, blk>>>(z, Wq, bq, q, N_ASSET, DLAT, DLAT, 1.0f);
    sgemm_nt<<<gp, blk>>>(z, Wk, bk, k, N_ASSET, DLAT, DLAT, 1.0f);
    sgemm_nt<<<gp, blk>>>(z, Wv, bv, v, N_ASSET, DLAT, DLAT, 1.0f);

    // scores = q @ k^T * d^-0.5   [8192, 8192]
    dim3 gs(N_ASSET / BN, N_ASSET / BM);  // 64 x 64
    const float scale = 1.0f / sqrtf((float)DLAT);
    sgemm_nt<<<gs, blk>>>(q, k, nullptr, s, N_ASSET, N_ASSET, DLAT, scale);

    // row softmax
    softmax_rows<<<N_ASSET, blk>>>(s, N_ASSET);

    // h = attn @ v   [8192, 512] -> d_out
    dim3 gh(DLAT / BN, N_ASSET / BM);     // 4 x 64
    sgemm_nn<<<gh, blk>>>(s, v, out, N_ASSET, DLAT, N_ASSET);
}

// round 3
// speedup vs baseline: 2.1373x; 2.1373x over previous
#include <cuda_runtime.h>
#include <cuda_bf16.h>
#include <math.h>
#include <stdint.h>

#define N_ASSET 8192
#define DLAT    512

// ---------------------------------------------------------------------------
// Scratch (__device__ globals; allocation-free rule)
// ---------------------------------------------------------------------------
__device__ __nv_bfloat16 g_zh[(size_t)N_ASSET * DLAT];
__device__ __nv_bfloat16 g_zl[(size_t)N_ASSET * DLAT];
__device__ __nv_bfloat16 g_wh[3][(size_t)DLAT * DLAT];
__device__ __nv_bfloat16 g_wl[3][(size_t)DLAT * DLAT];
__device__ __nv_bfloat16 g_qh[(size_t)N_ASSET * DLAT];
__device__ __nv_bfloat16 g_ql[(size_t)N_ASSET * DLAT];
__device__ __nv_bfloat16 g_kh[(size_t)N_ASSET * DLAT];
__device__ __nv_bfloat16 g_kl[(size_t)N_ASSET * DLAT];
__device__ __nv_bfloat16 g_vh[(size_t)N_ASSET * DLAT];    // v hi  [N][D]
__device__ __nv_bfloat16 g_vl[(size_t)N_ASSET * DLAT];    // v lo  [N][D]
__device__ __nv_bfloat16 g_vth[(size_t)DLAT * N_ASSET];   // v^T hi [D][N]
__device__ __nv_bfloat16 g_vtl[(size_t)DLAT * N_ASSET];   // v^T lo [D][N]
__device__ float         g_s[(size_t)N_ASSET * N_ASSET];  // fp32 scores
__device__ __nv_bfloat16 g_ah[(size_t)N_ASSET * N_ASSET]; // attn hi
__device__ __nv_bfloat16 g_al[(size_t)N_ASSET * N_ASSET]; // attn lo

// ---------------------------------------------------------------------------
// fp32 -> (hi, lo) bf16 split
// ---------------------------------------------------------------------------
__device__ __forceinline__ void split2(float x, __nv_bfloat16& h, __nv_bfloat16& l) {
    h = __float2bfloat16(x);
    l = __float2bfloat16(x - __bfloat162float(h));
}

__global__ __launch_bounds__(256)
void split_kernel(const float* __restrict__ x, __nv_bfloat16* __restrict__ h,
                  __nv_bfloat16* __restrict__ l, size_t n)
{
    size_t i = (size_t)blockIdx.x * blockDim.x + threadIdx.x;
    size_t stride = (size_t)gridDim.x * blockDim.x;
    for (; i < n; i += stride) {
        __nv_bfloat16 hh, ll;
        split2(x[i], hh, ll);
        h[i] = hh; l[i] = ll;
    }
}

// bf16 transpose: x[rows][cols] -> y[cols][rows]
__global__ __launch_bounds__(256)
void trans_bf16_kernel(const __nv_bfloat16* __restrict__ x,
                       __nv_bfloat16* __restrict__ y, int rows, int cols)
{
    __shared__ __nv_bfloat16 t[32][33];
    const int bx = blockIdx.x * 32;   // col base in x
    const int by = blockIdx.y * 32;   // row base in x
    const int tx = threadIdx.x, ty = threadIdx.y;

    #pragma unroll
    for (int j = 0; j < 4; ++j)
        t[ty + j * 8][tx] = x[(size_t)(by + ty + j * 8) * cols + bx + tx];
    __syncthreads();

    #pragma unroll
    for (int j = 0; j < 4; ++j)
        y[(size_t)(bx + ty + j * 8) * rows + by + tx] = t[tx][ty + j * 8];
}

// ---------------------------------------------------------------------------
// bf16x2-split NT GEMM on tensor cores:
//   C[M][N] = scale * (A[M][K] @ B[N][K]^T) + bias[N]
//   A ~ Ah+Al, B ~ Bh+Bl; computed as Ah*Bh + Ah*Bl + Al*Bh in fp32 acc.
// Block 128x128x16, 8 warps (2x4) of 64x32, cp.async double buffer.
// Output modes: fp32 C, or fused (hi,lo) split pair.
// ---------------------------------------------------------------------------
#define BM 128
#define BN 128
#define BK 16
#define SKS 24   // smem row stride (bf16 elems): conflict-free fragment loads

__device__ __forceinline__ void cp16(void* dst, const void* src) {
    unsigned sd = (unsigned)__cvta_generic_to_shared(dst);
    asm volatile("cp.async.cg.shared.global [%0], [%1], 16;\n" :: "r"(sd), "l"(src));
}

#define MMA_BF16(d, a0, a1, a2, a3, b0, b1)                                     \
    asm volatile(                                                               \
        "mma.sync.aligned.m16n8k16.row.col.f32.bf16.bf16.f32 "                  \
        "{%0,%1,%2,%3}, {%4,%5,%6,%7}, {%8,%9}, {%0,%1,%2,%3};\n"               \
        : "+f"(d[0]), "+f"(d[1]), "+f"(d[2]), "+f"(d[3])                        \
        : "r"(a0), "r"(a1), "r"(a2), "r"(a3), "r"(b0), "r"(b1))

__global__ __launch_bounds__(256, 2)
void gemm_bf16x2_nt(const __nv_bfloat16* __restrict__ Ah, const __nv_bfloat16* __restrict__ Al,
                    const __nv_bfloat16* __restrict__ Bh, const __nv_bfloat16* __restrict__ Bl,
                    const float* __restrict__ bias,
                    float* __restrict__ C,                 // fp32 out (may be null)
                    __nv_bfloat16* __restrict__ Oh,        // split out (may be null)
                    __nv_bfloat16* __restrict__ Ol,
                    int M, int N, int K, float scale)
{
    __shared__ __nv_bfloat16 sAh[2][BM][SKS], sAl[2][BM][SKS];
    __shared__ __nv_bfloat16 sBh[2][BN][SKS], sBl[2][BN][SKS];

    const int tid = threadIdx.x, lane = tid & 31, wid = tid >> 5;
    const int bm = blockIdx.y * BM, bn = blockIdx.x * BN;
    const int wm = (wid >> 2) * 64, wn = (wid & 3) * 32;
    const int g = lane >> 2, tg = lane & 3;

    float acc[4][4][4];
    #pragma unroll
    for (int i = 0; i < 4; ++i)
        #pragma unroll
        for (int j = 0; j < 4; ++j)
            #pragma unroll
            for (int q = 0; q < 4; ++q) acc[i][j][q] = 0.0f;

    // loader mapping: 256 threads -> 128 rows x 2 sixteen-byte halves
    const int lr = tid >> 1, lh = tid & 1;
    const size_t aoff = (size_t)(bm + lr) * K + lh * 8;
    const size_t boff = (size_t)(bn + lr) * K + lh * 8;

    const int KT = K / BK;

    {
        cp16(&sAh[0][lr][lh * 8], Ah + aoff);
        cp16(&sAl[0][lr][lh * 8], Al + aoff);
        cp16(&sBh[0][lr][lh * 8], Bh + boff);
        cp16(&sBl[0][lr][lh * 8], Bl + boff);
        asm volatile("cp.async.commit_group;\n");
    }

    for (int kt = 0; kt < KT; ++kt) {
        const int cur = kt & 1;
        if (kt + 1 < KT) {
            const int nxt = cur ^ 1;
            const size_t ko = (size_t)(kt + 1) * BK;
            cp16(&sAh[nxt][lr][lh * 8], Ah + aoff + ko);
            cp16(&sAl[nxt][lr][lh * 8], Al + aoff + ko);
            cp16(&sBh[nxt][lr][lh * 8], Bh + boff + ko);
            cp16(&sBl[nxt][lr][lh * 8], Bl + boff + ko);
            asm volatile("cp.async.commit_group;\n");
            asm volatile("cp.async.wait_group 1;\n");
        } else {
            asm volatile("cp.async.wait_group 0;\n");
        }
        __syncthreads();

        uint32_t bh[4][2], bl[4][2];
        #pragma unroll
        for (int ni = 0; ni < 4; ++ni) {
            const __nv_bfloat16* pbh = &sBh[cur][wn + ni * 8 + g][tg * 2];
            const __nv_bfloat16* pbl = &sBl[cur][wn + ni * 8 + g][tg * 2];
            bh[ni][0] = *(const uint32_t*)pbh;
            bh[ni][1] = *(const uint32_t*)(pbh + 8);
            bl[ni][0] = *(const uint32_t*)pbl;
            bl[ni][1] = *(const uint32_t*)(pbl + 8);
        }

        #pragma unroll
        for (int mi = 0; mi < 4; ++mi) {
            const int r0 = wm + mi * 16 + g;
            const __nv_bfloat16* pah0 = &sAh[cur][r0][tg * 2];
            const __nv_bfloat16* pah1 = &sAh[cur][r0 + 8][tg * 2];
            const __nv_bfloat16* pal0 = &sAl[cur][r0][tg * 2];
            const __nv_bfloat16* pal1 = &sAl[cur][r0 + 8][tg * 2];
            uint32_t ah0 = *(const uint32_t*)pah0;
            uint32_t ah1 = *(const uint32_t*)pah1;
            uint32_t ah2 = *(const uint32_t*)(pah0 + 8);
            uint32_t ah3 = *(const uint32_t*)(pah1 + 8);
            uint32_t al0 = *(const uint32_t*)pal0;
            uint32_t al1 = *(const uint32_t*)pal1;
            uint32_t al2 = *(const uint32_t*)(pal0 + 8);
            uint32_t al3 = *(const uint32_t*)(pal1 + 8);

            #pragma unroll
            for (int ni = 0; ni < 4; ++ni) {
                MMA_BF16(acc[mi][ni], ah0, ah1, ah2, ah3, bh[ni][0], bh[ni][1]);
                MMA_BF16(acc[mi][ni], ah0, ah1, ah2, ah3, bl[ni][0], bl[ni][1]);
                MMA_BF16(acc[mi][ni], al0, al1, al2, al3, bh[ni][0], bh[ni][1]);
            }
        }
        __syncthreads();
    }

    // epilogue
    #pragma unroll
    for (int mi = 0; mi < 4; ++mi) {
        const int row0 = bm + wm + mi * 16 + g;
        #pragma unroll
        for (int ni = 0; ni < 4; ++ni) {
            const int col = bn + wn + ni * 8 + tg * 2;
            const float b0 = bias ? bias[col] : 0.0f;
            const float b1 = bias ? bias[col + 1] : 0.0f;
            float r00 = acc[mi][ni][0] * scale + b0;
            float r01 = acc[mi][ni][1] * scale + b1;
            float r10 = acc[mi][ni][2] * scale + b0;
            float r11 = acc[mi][ni][3] * scale + b1;
            if (C) {
                C[(size_t)row0 * N + col]           = r00;
                C[(size_t)row0 * N + col + 1]       = r01;
                C[(size_t)(row0 + 8) * N + col]     = r10;
                C[(size_t)(row0 + 8) * N + col + 1] = r11;
            }
            if (Oh) {
                __nv_bfloat16 h0, l0, h1, l1;
                split2(r00, h0, l0); split2(r01, h1, l1);
                __nv_bfloat162 hp = {h0, h1}, lp = {l0, l1};
                *(__nv_bfloat162*)&Oh[(size_t)row0 * N + col] = hp;
                *(__nv_bfloat162*)&Ol[(size_t)row0 * N + col] = lp;
                split2(r10, h0, l0); split2(r11, h1, l1);
                __nv_bfloat162 hp2 = {h0, h1}, lp2 = {l0, l1};
                *(__nv_bfloat162*)&Oh[(size_t)(row0 + 8) * N + col] = hp2;
                *(__nv_bfloat162*)&Ol[(size_t)(row0 + 8) * N + col] = lp2;
            }
        }
    }
}

// ---------------------------------------------------------------------------
// Row softmax (N=8192) fused with bf16 hi/lo split of attn
// ---------------------------------------------------------------------------
__global__ __launch_bounds__(256)
void softmax_split_rows(const float* __restrict__ S,
                        __nv_bfloat16* __restrict__ Ah,
                        __nv_bfloat16* __restrict__ Al)
{
    const int tid = threadIdx.x;
    const size_t rowoff = (size_t)blockIdx.x * N_ASSET;
    const float* s = S + rowoff;

    float v[32];
    float m = -3.4e38f;
    #pragma unroll
    for (int i = 0; i < 32; ++i) {
        v[i] = s[i * 256 + tid];
        m = fmaxf(m, v[i]);
    }

    __shared__ float red[8];
    __shared__ float bcast;

    #pragma unroll
    for (int o = 16; o > 0; o >>= 1) m = fmaxf(m, __shfl_xor_sync(0xffffffffu, m, o));
    if ((tid & 31) == 0) red[tid >> 5] = m;
    __syncthreads();
    if (tid < 32) {
        float t = (tid < 8) ? red[tid] : -3.4e38f;
        #pragma unroll
        for (int o = 4; o > 0; o >>= 1) t = fmaxf(t, __shfl_xor_sync(0xffffffffu, t, o));
        if (tid == 0) bcast = t;
    }
    __syncthreads();
    m = bcast;
    __syncthreads();

    float sum = 0.0f;
    #pragma unroll
    for (int i = 0; i < 32; ++i) {
        v[i] = __expf(v[i] - m);
        sum += v[i];
    }
    #pragma unroll
    for (int o = 16; o > 0; o >>= 1) sum += __shfl_xor_sync(0xffffffffu, sum, o);
    if ((tid & 31) == 0) red[tid >> 5] = sum;
    __syncthreads();
    if (tid < 32) {
        float t = (tid < 8) ? red[tid] : 0.0f;
        #pragma unroll
        for (int o = 4; o > 0; o >>= 1) t += __shfl_xor_sync(0xffffffffu, t, o);
        if (tid == 0) bcast = t;
    }
    __syncthreads();

    const float inv = 1.0f / bcast;
    #pragma unroll
    for (int i = 0; i < 32; ++i) {
        float a = v[i] * inv;
        __nv_bfloat16 hh, ll;
        split2(a, hh, ll);
        Ah[rowoff + i * 256 + tid] = hh;
        Al[rowoff + i * 256 + tid] = ll;
    }
}

// ---------------------------------------------------------------------------
// kernel_launch
// Inputs: z, Wq, bq, Wk, bk, Wv, bv  (fp32). Output: h (8192 x 512) fp32.
// ---------------------------------------------------------------------------
extern "C" void kernel_launch(void* const* d_in, const int* in_sizes, int n_in,
                              void* d_out, int out_size)
{
    const float* z  = (const float*)d_in[0];
    const float* Wq = (const float*)d_in[1];
    const float* bq = (const float*)d_in[2];
    const float* Wk = (const float*)d_in[3];
    const float* bk = (const float*)d_in[4];
    const float* Wv = (const float*)d_in[5];
    const float* bv = (const float*)d_in[6];
    float* out = (float*)d_out;

    __nv_bfloat16 *zh, *zl, *wh, *wl, *qh, *ql, *kh, *kl, *vh, *vl, *vth, *vtl, *ah, *al;
    float *s;
    cudaGetSymbolAddress((void**)&zh, g_zh);
    cudaGetSymbolAddress((void**)&zl, g_zl);
    cudaGetSymbolAddress((void**)&wh, g_wh);
    cudaGetSymbolAddress((void**)&wl, g_wl);
    cudaGetSymbolAddress((void**)&qh, g_qh);
    cudaGetSymbolAddress((void**)&ql, g_ql);
    cudaGetSymbolAddress((void**)&kh, g_kh);
    cudaGetSymbolAddress((void**)&kl, g_kl);
    cudaGetSymbolAddress((void**)&vh, g_vh);
    cudaGetSymbolAddress((void**)&vl, g_vl);
    cudaGetSymbolAddress((void**)&vth, g_vth);
    cudaGetSymbolAddress((void**)&vtl, g_vtl);
    cudaGetSymbolAddress((void**)&s, g_s);
    cudaGetSymbolAddress((void**)&ah, g_ah);
    cudaGetSymbolAddress((void**)&al, g_al);

    const size_t zd = (size_t)N_ASSET * DLAT;
    const size_t wd = (size_t)DLAT * DLAT;

    // 1. split inputs
    split_kernel<<<512, 256>>>(z, zh, zl, zd);
    split_kernel<<<128, 256>>>(Wq, wh + 0 * wd, wl + 0 * wd, wd);
    split_kernel<<<128, 256>>>(Wk, wh + 1 * wd, wl + 1 * wd, wd);
    split_kernel<<<128, 256>>>(Wv, wh + 2 * wd, wl + 2 * wd, wd);

    // 2. QKV projections with fused output split: [8192,512] = z @ W^T + b
    dim3 blk(256);
    dim3 gp(DLAT / BN, N_ASSET / BM);  // 4 x 64
    gemm_bf16x2_nt<<<gp, blk>>>(zh, zl, wh + 0 * wd, wl + 0 * wd, bq,
                                nullptr, qh, ql, N_ASSET, DLAT, DLAT, 1.0f);
    gemm_bf16x2_nt<<<gp, blk>>>(zh, zl, wh + 1 * wd, wl + 1 * wd, bk,
                                nullptr, kh, kl, N_ASSET, DLAT, DLAT, 1.0f);
    gemm_bf16x2_nt<<<gp, blk>>>(zh, zl, wh + 2 * wd, wl + 2 * wd, bv,
                                nullptr, vh, vl, N_ASSET, DLAT, DLAT, 1.0f);

    // 3. transpose v hi/lo -> [D][N]
    {
        dim3 tb(32, 8);
        dim3 tg(DLAT / 32, N_ASSET / 32);  // 16 x 256
        trans_bf16_kernel<<<tg, tb>>>(vh, vth, N_ASSET, DLAT);
        trans_bf16_kernel<<<tg, tb>>>(vl, vtl, N_ASSET, DLAT);
    }

    // 4. scores = q @ k^T * d^-0.5  (fp32 out)
    dim3 gs(N_ASSET / BN, N_ASSET / BM);  // 64 x 64
    const float scale = 1.0f / sqrtf((float)DLAT);
    gemm_bf16x2_nt<<<gs, blk>>>(qh, ql, kh, kl, nullptr,
                                s, nullptr, nullptr, N_ASSET, N_ASSET, DLAT, scale);

    // 5. softmax + split -> attn hi/lo
    softmax_split_rows<<<N_ASSET, blk>>>(s, ah, al);

    // 6. h = attn @ (v^T)^T  -> NT GEMM with B = v^T [512][8192], fp32 out
    dim3 gh(DLAT / BN, N_ASSET / BM);  // 4 x 64
    gemm_bf16x2_nt<<<gh, blk>>>(ah, al, vth, vtl, nullptr,
                                out, nullptr, nullptr, N_ASSET, DLAT, N_ASSET, 1.0f);
}

// round 5
// speedup vs baseline: 2.5768x; 1.2056x over previous
#include <cuda_runtime.h>
#include <cuda_bf16.h>
#include <math.h>
#include <stdint.h>

#define N_ASSET 8192
#define DLAT    512

// ---------------------------------------------------------------------------
// Scratch (__device__ globals; allocation-free rule)
// ---------------------------------------------------------------------------
__device__ __nv_bfloat16 g_zh[(size_t)N_ASSET * DLAT];
__device__ __nv_bfloat16 g_zl[(size_t)N_ASSET * DLAT];
__device__ __nv_bfloat16 g_wh[3][(size_t)DLAT * DLAT];
__device__ __nv_bfloat16 g_wl[3][(size_t)DLAT * DLAT];
__device__ __nv_bfloat16 g_qh[(size_t)N_ASSET * DLAT];
__device__ __nv_bfloat16 g_ql[(size_t)N_ASSET * DLAT];
__device__ __nv_bfloat16 g_kh[(size_t)N_ASSET * DLAT];
__device__ __nv_bfloat16 g_kl[(size_t)N_ASSET * DLAT];
__device__ __nv_bfloat16 g_vh[(size_t)N_ASSET * DLAT];    // v hi  [N][D]
__device__ __nv_bfloat16 g_vl[(size_t)N_ASSET * DLAT];    // v lo  [N][D]
__device__ __nv_bfloat16 g_vth[(size_t)DLAT * N_ASSET];   // v^T hi [D][N]
__device__ __nv_bfloat16 g_vtl[(size_t)DLAT * N_ASSET];   // v^T lo [D][N]
__device__ float         g_s[(size_t)N_ASSET * N_ASSET];  // fp32 scores
__device__ __nv_bfloat16 g_ah[(size_t)N_ASSET * N_ASSET]; // attn hi
__device__ __nv_bfloat16 g_al[(size_t)N_ASSET * N_ASSET]; // attn lo

// ---------------------------------------------------------------------------
// Helpers
// ---------------------------------------------------------------------------
__device__ __forceinline__ void split2(float x, __nv_bfloat16& h, __nv_bfloat16& l) {
    h = __float2bfloat16(x);
    l = __float2bfloat16(x - __bfloat162float(h));
}

__device__ __forceinline__ uint32_t smem_u32(const void* p) {
    uint32_t a;
    asm("{ .reg .u64 t; cvta.to.shared.u64 t, %1; cvt.u32.u64 %0, t; }" : "=r"(a) : "l"(p));
    return a;
}

__device__ __forceinline__ void cp16s(uint32_t sdst, const void* src) {
    asm volatile("cp.async.cg.shared.global [%0], [%1], 16;\n" :: "r"(sdst), "l"(src));
}

#define LDSM_X4(r0, r1, r2, r3, addr) \
    asm volatile("ldmatrix.sync.aligned.m8n8.x4.shared.b16 {%0,%1,%2,%3}, [%4];" \
        : "=r"(r0), "=r"(r1), "=r"(r2), "=r"(r3) : "r"(addr))

#define MMA_BF16(d, a0, a1, a2, a3, b0, b1)                                     \
    asm volatile(                                                               \
        "mma.sync.aligned.m16n8k16.row.col.f32.bf16.bf16.f32 "                  \
        "{%0,%1,%2,%3}, {%4,%5,%6,%7}, {%8,%9}, {%0,%1,%2,%3};\n"               \
        : "+f"(d[0]), "+f"(d[1]), "+f"(d[2]), "+f"(d[3])                        \
        : "r"(a0), "r"(a1), "r"(a2), "r"(a3), "r"(b0), "r"(b1))

// ---------------------------------------------------------------------------
// Elementwise split / transpose kernels (unchanged)
// ---------------------------------------------------------------------------
__global__ __launch_bounds__(256)
void split_kernel(const float* __restrict__ x, __nv_bfloat16* __restrict__ h,
                  __nv_bfloat16* __restrict__ l, size_t n)
{
    size_t i = (size_t)blockIdx.x * blockDim.x + threadIdx.x;
    size_t stride = (size_t)gridDim.x * blockDim.x;
    for (; i < n; i += stride) {
        __nv_bfloat16 hh, ll;
        split2(x[i], hh, ll);
        h[i] = hh; l[i] = ll;
    }
}

__global__ __launch_bounds__(256)
void trans_bf16_kernel(const __nv_bfloat16* __restrict__ x,
                       __nv_bfloat16* __restrict__ y, int rows, int cols)
{
    __shared__ __nv_bfloat16 t[32][33];
    const int bx = blockIdx.x * 32;
    const int by = blockIdx.y * 32;
    const int tx = threadIdx.x, ty = threadIdx.y;

    #pragma unroll
    for (int j = 0; j < 4; ++j)
        t[ty + j * 8][tx] = x[(size_t)(by + ty + j * 8) * cols + bx + tx];
    __syncthreads();

    #pragma unroll
    for (int j = 0; j < 4; ++j)
        y[(size_t)(bx + ty + j * 8) * rows + by + tx] = t[tx][ty + j * 8];
}

// ---------------------------------------------------------------------------
// bf16x2-split NT GEMM on tensor cores (ldmatrix + BK=32):
//   C[M][N] = scale * (A[M][K] @ B[N][K]^T) + bias[N]   (A ~ Ah+Al, B ~ Bh+Bl)
// Block 128x128x32, 8 warps (2x4) of 64x32, cp.async double buffer.
// Smem tile: 128 rows x 80 B (64 B data + 16 B pad) — LDSM conflict-free.
// ---------------------------------------------------------------------------
#define GBK 32
#define ROWB 80                              // bytes per smem row
#define TILE_B (128 * ROWB)                  // 10240
#define STAGE_B (4 * TILE_B)                 // 40960
#define SMEM_DYN (2 * STAGE_B)               // 81920

__global__ __launch_bounds__(256, 2)
void gemm_bf16x2_nt(const __nv_bfloat16* __restrict__ Ah, const __nv_bfloat16* __restrict__ Al,
                    const __nv_bfloat16* __restrict__ Bh, const __nv_bfloat16* __restrict__ Bl,
                    const float* __restrict__ bias,
                    float* __restrict__ C,
                    __nv_bfloat16* __restrict__ Oh, __nv_bfloat16* __restrict__ Ol,
                    int M, int N, int K, float scale)
{
    extern __shared__ __align__(128) char dsm[];
    const uint32_t sb = smem_u32(dsm);

    const int tid = threadIdx.x, lane = tid & 31, wid = tid >> 5;
    const int bm = blockIdx.y * 128, bn = blockIdx.x * 128;
    const int wm = (wid >> 2) * 64, wn = (wid & 3) * 32;
    const int g = lane >> 2, tg = lane & 3;

    float acc[4][4][4];
    #pragma unroll
    for (int i = 0; i < 4; ++i)
        #pragma unroll
        for (int j = 0; j < 4; ++j)
            #pragma unroll
            for (int q = 0; q < 4; ++q) acc[i][j][q] = 0.0f;

    // loader role: 64 threads per tile {Ah, Al, Bh, Bl}
    const int t4 = tid >> 6, w6 = tid & 63;
    const __nv_bfloat16* gsrc = (t4 == 0) ? Ah : (t4 == 1) ? Al : (t4 == 2) ? Bh : Bl;
    const int rb = (t4 < 2) ? bm : bn;
    const uint32_t tbase = sb + t4 * TILE_B;

    const int KT = K / GBK;

    auto load_stage = [&](int kt, int s) {
        const size_t k0 = (size_t)kt * GBK;
        const uint32_t stb = tbase + s * STAGE_B;
        #pragma unroll
        for (int j = 0; j < 8; ++j) {
            const int idx = w6 + j * 64;
            const int r = idx >> 2, h = idx & 3;
            cp16s(stb + r * ROWB + h * 16,
                  gsrc + (size_t)(rb + r) * K + k0 + h * 8);
        }
    };

    // prologue
    load_stage(0, 0);
    asm volatile("cp.async.commit_group;\n");

    // fragment smem addressing (per-lane constants)
    // A: row = (mi*16) + (lane&15), chunk = (lane>>4)*16B
    const uint32_t aRowOff = (uint32_t)(wm + (lane & 15)) * ROWB + (uint32_t)(lane >> 4) * 16;
    // B: n = pair*16 + ((lane>>4)<<3) + (lane&7), chunk = ((lane>>3)&1)*16B
    const uint32_t bRowOff = (uint32_t)(wn + ((lane >> 4) << 3) + (lane & 7)) * ROWB
                           + (uint32_t)((lane >> 3) & 1) * 16;

    for (int kt = 0; kt < KT; ++kt) {
        const int s = kt & 1;
        if (kt + 1 < KT) {
            load_stage(kt + 1, s ^ 1);
            asm volatile("cp.async.commit_group;\n");
            asm volatile("cp.async.wait_group 1;\n");
        } else {
            asm volatile("cp.async.wait_group 0;\n");
        }
        __syncthreads();

        const uint32_t stg = sb + s * STAGE_B;
        const uint32_t aH = stg + aRowOff;              // tile 0
        const uint32_t aL = stg + TILE_B + aRowOff;     // tile 1
        const uint32_t bH = stg + 2 * TILE_B + bRowOff; // tile 2
        const uint32_t bL = stg + 3 * TILE_B + bRowOff; // tile 3

        #pragma unroll
        for (int ks2 = 0; ks2 < 2; ++ks2) {
            const uint32_t ko = ks2 * 32;

            uint32_t bh[4][2], bl[4][2];
            #pragma unroll
            for (int p = 0; p < 2; ++p) {
                LDSM_X4(bh[2 * p][0], bh[2 * p][1], bh[2 * p + 1][0], bh[2 * p + 1][1],
                        bH + p * (16 * ROWB) + ko);
                LDSM_X4(bl[2 * p][0], bl[2 * p][1], bl[2 * p + 1][0], bl[2 * p + 1][1],
                        bL + p * (16 * ROWB) + ko);
            }

            #pragma unroll
            for (int mi = 0; mi < 4; ++mi) {
                uint32_t ah0, ah1, ah2, ah3, al0, al1, al2, al3;
                LDSM_X4(ah0, ah1, ah2, ah3, aH + mi * (16 * ROWB) + ko);
                LDSM_X4(al0, al1, al2, al3, aL + mi * (16 * ROWB) + ko);

                #pragma unroll
                for (int ni = 0; ni < 4; ++ni) {
                    MMA_BF16(acc[mi][ni], ah0, ah1, ah2, ah3, bh[ni][0], bh[ni][1]);
                    MMA_BF16(acc[mi][ni], ah0, ah1, ah2, ah3, bl[ni][0], bl[ni][1]);
                    MMA_BF16(acc[mi][ni], al0, al1, al2, al3, bh[ni][0], bh[ni][1]);
                }
            }
        }
        __syncthreads();
    }

    // epilogue (mma acc layout: rows g, g+8; cols tg*2, tg*2+1)
    #pragma unroll
    for (int mi = 0; mi < 4; ++mi) {
        const int row0 = bm + wm + mi * 16 + g;
        #pragma unroll
        for (int ni = 0; ni < 4; ++ni) {
            const int col = bn + wn + ni * 8 + tg * 2;
            const float b0 = bias ? bias[col] : 0.0f;
            const float b1 = bias ? bias[col + 1] : 0.0f;
            float r00 = acc[mi][ni][0] * scale + b0;
            float r01 = acc[mi][ni][1] * scale + b1;
            float r10 = acc[mi][ni][2] * scale + b0;
            float r11 = acc[mi][ni][3] * scale + b1;
            if (C) {
                C[(size_t)row0 * N + col]           = r00;
                C[(size_t)row0 * N + col + 1]       = r01;
                C[(size_t)(row0 + 8) * N + col]     = r10;
                C[(size_t)(row0 + 8) * N + col + 1] = r11;
            }
            if (Oh) {
                __nv_bfloat16 h0, l0, h1, l1;
                split2(r00, h0, l0); split2(r01, h1, l1);
                __nv_bfloat162 hp = {h0, h1}, lp = {l0, l1};
                *(__nv_bfloat162*)&Oh[(size_t)row0 * N + col] = hp;
                *(__nv_bfloat162*)&Ol[(size_t)row0 * N + col] = lp;
                split2(r10, h0, l0); split2(r11, h1, l1);
                __nv_bfloat162 hp2 = {h0, h1}, lp2 = {l0, l1};
                *(__nv_bfloat162*)&Oh[(size_t)(row0 + 8) * N + col] = hp2;
                *(__nv_bfloat162*)&Ol[(size_t)(row0 + 8) * N + col] = lp2;
            }
        }
    }
}

// ---------------------------------------------------------------------------
// Row softmax (N=8192) fused with bf16 hi/lo split of attn (unchanged)
// ---------------------------------------------------------------------------
__global__ __launch_bounds__(256)
void softmax_split_rows(const float* __restrict__ S,
                        __nv_bfloat16* __restrict__ Ah,
                        __nv_bfloat16* __restrict__ Al)
{
    const int tid = threadIdx.x;
    const size_t rowoff = (size_t)blockIdx.x * N_ASSET;
    const float* s = S + rowoff;

    float v[32];
    float m = -3.4e38f;
    #pragma unroll
    for (int i = 0; i < 32; ++i) {
        v[i] = s[i * 256 + tid];
        m = fmaxf(m, v[i]);
    }

    __shared__ float red[8];
    __shared__ float bcast;

    #pragma unroll
    for (int o = 16; o > 0; o >>= 1) m = fmaxf(m, __shfl_xor_sync(0xffffffffu, m, o));
    if ((tid & 31) == 0) red[tid >> 5] = m;
    __syncthreads();
    if (tid < 32) {
        float t = (tid < 8) ? red[tid] : -3.4e38f;
        #pragma unroll
        for (int o = 4; o > 0; o >>= 1) t = fmaxf(t, __shfl_xor_sync(0xffffffffu, t, o));
        if (tid == 0) bcast = t;
    }
    __syncthreads();
    m = bcast;
    __syncthreads();

    float sum = 0.0f;
    #pragma unroll
    for (int i = 0; i < 32; ++i) {
        v[i] = __expf(v[i] - m);
        sum += v[i];
    }
    #pragma unroll
    for (int o = 16; o > 0; o >>= 1) sum += __shfl_xor_sync(0xffffffffu, sum, o);
    if ((tid & 31) == 0) red[tid >> 5] = sum;
    __syncthreads();
    if (tid < 32) {
        float t = (tid < 8) ? red[tid] : 0.0f;
        #pragma unroll
        for (int o = 4; o > 0; o >>= 1) t += __shfl_xor_sync(0xffffffffu, t, o);
        if (tid == 0) bcast = t;
    }
    __syncthreads();

    const float inv = 1.0f / bcast;
    #pragma unroll
    for (int i = 0; i < 32; ++i) {
        float a = v[i] * inv;
        __nv_bfloat16 hh, ll;
        split2(a, hh, ll);
        Ah[rowoff + i * 256 + tid] = hh;
        Al[rowoff + i * 256 + tid] = ll;
    }
}

// ---------------------------------------------------------------------------
// kernel_launch
// ---------------------------------------------------------------------------
extern "C" void kernel_launch(void* const* d_in, const int* in_sizes, int n_in,
                              void* d_out, int out_size)
{
    const float* z  = (const float*)d_in[0];
    const float* Wq = (const float*)d_in[1];
    const float* bq = (const float*)d_in[2];
    const float* Wk = (const float*)d_in[3];
    const float* bk = (const float*)d_in[4];
    const float* Wv = (const float*)d_in[5];
    const float* bv = (const float*)d_in[6];
    float* out = (float*)d_out;

    __nv_bfloat16 *zh, *zl, *wh, *wl, *qh, *ql, *kh, *kl, *vh, *vl, *vth, *vtl, *ah, *al;
    float *s;
    cudaGetSymbolAddress((void**)&zh, g_zh);
    cudaGetSymbolAddress((void**)&zl, g_zl);
    cudaGetSymbolAddress((void**)&wh, g_wh);
    cudaGetSymbolAddress((void**)&wl, g_wl);
    cudaGetSymbolAddress((void**)&qh, g_qh);
    cudaGetSymbolAddress((void**)&ql, g_ql);
    cudaGetSymbolAddress((void**)&kh, g_kh);
    cudaGetSymbolAddress((void**)&kl, g_kl);
    cudaGetSymbolAddress((void**)&vh, g_vh);
    cudaGetSymbolAddress((void**)&vl, g_vl);
    cudaGetSymbolAddress((void**)&vth, g_vth);
    cudaGetSymbolAddress((void**)&vtl, g_vtl);
    cudaGetSymbolAddress((void**)&s, g_s);
    cudaGetSymbolAddress((void**)&ah, g_ah);
    cudaGetSymbolAddress((void**)&al, g_al);

    cudaFuncSetAttribute(gemm_bf16x2_nt, cudaFuncAttributeMaxDynamicSharedMemorySize, SMEM_DYN);

    const size_t zd = (size_t)N_ASSET * DLAT;
    const size_t wd = (size_t)DLAT * DLAT;

    // 1. split inputs
    split_kernel<<<512, 256>>>(z, zh, zl, zd);
    split_kernel<<<128, 256>>>(Wq, wh + 0 * wd, wl + 0 * wd, wd);
    split_kernel<<<128, 256>>>(Wk, wh + 1 * wd, wl + 1 * wd, wd);
    split_kernel<<<128, 256>>>(Wv, wh + 2 * wd, wl + 2 * wd, wd);

    // 2. QKV projections (fused split outputs)
    dim3 blk(256);
    dim3 gp(DLAT / 128, N_ASSET / 128);  // 4 x 64
    gemm_bf16x2_nt<<<gp, blk, SMEM_DYN>>>(zh, zl, wh + 0 * wd, wl + 0 * wd, bq,
                                          nullptr, qh, ql, N_ASSET, DLAT, DLAT, 1.0f);
    gemm_bf16x2_nt<<<gp, blk, SMEM_DYN>>>(zh, zl, wh + 1 * wd, wl + 1 * wd, bk,
                                          nullptr, kh, kl, N_ASSET, DLAT, DLAT, 1.0f);
    gemm_bf16x2_nt<<<gp, blk, SMEM_DYN>>>(zh, zl, wh + 2 * wd, wl + 2 * wd, bv,
                                          nullptr, vh, vl, N_ASSET, DLAT, DLAT, 1.0f);

    // 3. transpose v hi/lo -> [D][N]
    {
        dim3 tb(32, 8);
        dim3 tg(DLAT / 32, N_ASSET / 32);
        trans_bf16_kernel<<<tg, tb>>>(vh, vth, N_ASSET, DLAT);
        trans_bf16_kernel<<<tg, tb>>>(vl, vtl, N_ASSET, DLAT);
    }

    // 4. scores = q @ k^T * d^-0.5 (fp32 out)
    dim3 gs(N_ASSET / 128, N_ASSET / 128);  // 64 x 64
    const float scale = 1.0f / sqrtf((float)DLAT);
    gemm_bf16x2_nt<<<gs, blk, SMEM_DYN>>>(qh, ql, kh, kl, nullptr,
                                          s, nullptr, nullptr, N_ASSET, N_ASSET, DLAT, scale);

    // 5. softmax + split -> attn hi/lo
    softmax_split_rows<<<N_ASSET, blk>>>(s, ah, al);

    // 6. h = attn @ v  (B = v^T [512][8192]), fp32 out
    dim3 gh(DLAT / 128, N_ASSET / 128);  // 4 x 64
    gemm_bf16x2_nt<<<gh, blk, SMEM_DYN>>>(ah, al, vth, vtl, nullptr,
                                          out, nullptr, nullptr, N_ASSET, DLAT, N_ASSET, 1.0f);
}

// round 6
// speedup vs baseline: 3.6887x; 1.4315x over previous
#include <cuda_runtime.h>
#include <cuda_fp16.h>
#include <math.h>
#include <stdint.h>

#define N_ASSET 8192
#define DLAT    512

// ---------------------------------------------------------------------------
// Scratch (__device__ globals; allocation-free rule)
// ---------------------------------------------------------------------------
__device__ __half g_zh[(size_t)N_ASSET * DLAT];
__device__ __half g_wh[3][(size_t)DLAT * DLAT];
__device__ __half g_wl[3][(size_t)DLAT * DLAT];
__device__ __half g_qh[(size_t)N_ASSET * DLAT];
__device__ __half g_kh[(size_t)N_ASSET * DLAT];
__device__ __half g_kl[(size_t)N_ASSET * DLAT];
__device__ __half g_vh[(size_t)N_ASSET * DLAT];    // v hi  [N][D]
__device__ __half g_vl[(size_t)N_ASSET * DLAT];    // v lo  [N][D]
__device__ __half g_vth[(size_t)DLAT * N_ASSET];   // v^T hi [D][N]
__device__ __half g_vtl[(size_t)DLAT * N_ASSET];   // v^T lo [D][N]
__device__ float  g_s[(size_t)N_ASSET * N_ASSET];  // fp32 scores
__device__ __half g_ah[(size_t)N_ASSET * N_ASSET]; // attn hi

// ---------------------------------------------------------------------------
// Helpers
// ---------------------------------------------------------------------------
__device__ __forceinline__ void split2h(float x, __half& h, __half& l) {
    h = __float2half(x);
    l = __float2half(x - __half2float(h));
}

__device__ __forceinline__ uint32_t smem_u32(const void* p) {
    uint32_t a;
    asm("{ .reg .u64 t; cvta.to.shared.u64 t, %1; cvt.u32.u64 %0, t; }" : "=r"(a) : "l"(p));
    return a;
}

__device__ __forceinline__ void cp16s(uint32_t sdst, const void* src) {
    asm volatile("cp.async.cg.shared.global [%0], [%1], 16;\n" :: "r"(sdst), "l"(src));
}

#define LDSM_X4(r0, r1, r2, r3, addr) \
    asm volatile("ldmatrix.sync.aligned.m8n8.x4.shared.b16 {%0,%1,%2,%3}, [%4];" \
        : "=r"(r0), "=r"(r1), "=r"(r2), "=r"(r3) : "r"(addr))

#define MMA_F16(d, a0, a1, a2, a3, b0, b1)                                      \
    asm volatile(                                                               \
        "mma.sync.aligned.m16n8k16.row.col.f32.f16.f16.f32 "                    \
        "{%0,%1,%2,%3}, {%4,%5,%6,%7}, {%8,%9}, {%0,%1,%2,%3};\n"               \
        : "+f"(d[0]), "+f"(d[1]), "+f"(d[2]), "+f"(d[3])                        \
        : "r"(a0), "r"(a1), "r"(a2), "r"(a3), "r"(b0), "r"(b1))

// ---------------------------------------------------------------------------
// Elementwise kernels
// ---------------------------------------------------------------------------
__global__ __launch_bounds__(256)
void conv_half_kernel(const float* __restrict__ x, __half* __restrict__ h, size_t n)
{
    size_t i = (size_t)blockIdx.x * blockDim.x + threadIdx.x;
    size_t stride = (size_t)gridDim.x * blockDim.x;
    for (; i < n; i += stride) h[i] = __float2half(x[i]);
}

__global__ __launch_bounds__(256)
void split_half_kernel(const float* __restrict__ x, __half* __restrict__ h,
                       __half* __restrict__ l, size_t n)
{
    size_t i = (size_t)blockIdx.x * blockDim.x + threadIdx.x;
    size_t stride = (size_t)gridDim.x * blockDim.x;
    for (; i < n; i += stride) {
        __half hh, ll;
        split2h(x[i], hh, ll);
        h[i] = hh; l[i] = ll;
    }
}

__global__ __launch_bounds__(256)
void trans_half_kernel(const __half* __restrict__ x,
                       __half* __restrict__ y, int rows, int cols)
{
    __shared__ __half t[32][33];
    const int bx = blockIdx.x * 32;
    const int by = blockIdx.y * 32;
    const int tx = threadIdx.x, ty = threadIdx.y;

    #pragma unroll
    for (int j = 0; j < 4; ++j)
        t[ty + j * 8][tx] = x[(size_t)(by + ty + j * 8) * cols + bx + tx];
    __syncthreads();

    #pragma unroll
    for (int j = 0; j < 4; ++j)
        y[(size_t)(bx + ty + j * 8) * rows + by + tx] = t[tx][ty + j * 8];
}

// ---------------------------------------------------------------------------
// fp16 2-term split NT GEMM:
//   C[M][N] = scale * (A[M][K] @ (Bh+Bl)[N][K]^T) + bias[N]
//   (A is hi-only fp16; B carried to ~22 bits as Bh + Bl)
// Block 128x128x32, 8 warps (2x4) of 64x32, cp.async double buffer, ldmatrix.
// Smem: 3 tiles (Ah, Bh, Bl) x 128 rows x 80 B.
// ---------------------------------------------------------------------------
#define GBK 32
#define ROWB 80
#define TILE_B (128 * ROWB)                  // 10240
#define STAGE_B (3 * TILE_B)                 // 30720
#define SMEM_DYN (2 * STAGE_B)               // 61440

__global__ __launch_bounds__(256, 2)
void gemm_fp16x2_nt(const __half* __restrict__ Ah,
                    const __half* __restrict__ Bh, const __half* __restrict__ Bl,
                    const float* __restrict__ bias,
                    float* __restrict__ C,
                    __half* __restrict__ Oh, __half* __restrict__ Ol,
                    int M, int N, int K, float scale)
{
    extern __shared__ __align__(128) char dsm[];
    const uint32_t sb = smem_u32(dsm);

    const int tid = threadIdx.x, lane = tid & 31, wid = tid >> 5;
    const int bm = blockIdx.y * 128, bn = blockIdx.x * 128;
    const int wm = (wid >> 2) * 64, wn = (wid & 3) * 32;
    const int g = lane >> 2, tg = lane & 3;

    float acc[4][4][4];
    #pragma unroll
    for (int i = 0; i < 4; ++i)
        #pragma unroll
        for (int j = 0; j < 4; ++j)
            #pragma unroll
            for (int q = 0; q < 4; ++q) acc[i][j][q] = 0.0f;

    const int KT = K / GBK;

    // flat loader: 3 tiles x 512 chunks = 1536 cp16, 6 per thread
    const int lr = tid >> 2, lh = tid & 3;
    auto load_stage = [&](int kt, int s) {
        const size_t k0 = (size_t)kt * GBK;
        const uint32_t stb = sb + s * STAGE_B;
        #pragma unroll
        for (int j = 0; j < 6; ++j) {
            const int tile = j >> 1;                 // 0:Ah 1:Bh 2:Bl (const per j)
            const int r = ((j & 1) << 6) + lr;       // 0..127
            const __half* src =
                (tile == 0) ? Ah + (size_t)(bm + r) * K
              : (tile == 1) ? Bh + (size_t)(bn + r) * K
                            : Bl + (size_t)(bn + r) * K;
            cp16s(stb + tile * TILE_B + r * ROWB + lh * 16, src + k0 + lh * 8);
        }
    };

    load_stage(0, 0);
    asm volatile("cp.async.commit_group;\n");

    // fragment smem addressing (round-5-proven lane maps)
    const uint32_t aRowOff = (uint32_t)(wm + (lane & 15)) * ROWB + (uint32_t)(lane >> 4) * 16;
    const uint32_t bRowOff = (uint32_t)(wn + ((lane >> 4) << 3) + (lane & 7)) * ROWB
                           + (uint32_t)((lane >> 3) & 1) * 16;

    for (int kt = 0; kt < KT; ++kt) {
        const int s = kt & 1;
        if (kt + 1 < KT) {
            load_stage(kt + 1, s ^ 1);
            asm volatile("cp.async.commit_group;\n");
            asm volatile("cp.async.wait_group 1;\n");
        } else {
            asm volatile("cp.async.wait_group 0;\n");
        }
        __syncthreads();

        const uint32_t stg = sb + s * STAGE_B;
        const uint32_t aH = stg + aRowOff;
        const uint32_t bH = stg + TILE_B + bRowOff;
        const uint32_t bL = stg + 2 * TILE_B + bRowOff;

        #pragma unroll
        for (int ks2 = 0; ks2 < 2; ++ks2) {
            const uint32_t ko = ks2 * 32;

            uint32_t bh[4][2], bl[4][2];
            #pragma unroll
            for (int p = 0; p < 2; ++p) {
                LDSM_X4(bh[2 * p][0], bh[2 * p][1], bh[2 * p + 1][0], bh[2 * p + 1][1],
                        bH + p * (16 * ROWB) + ko);
                LDSM_X4(bl[2 * p][0], bl[2 * p][1], bl[2 * p + 1][0], bl[2 * p + 1][1],
                        bL + p * (16 * ROWB) + ko);
            }

            #pragma unroll
            for (int mi = 0; mi < 4; ++mi) {
                uint32_t a0, a1, a2, a3;
                LDSM_X4(a0, a1, a2, a3, aH + mi * (16 * ROWB) + ko);

                #pragma unroll
                for (int ni = 0; ni < 4; ++ni) {
                    MMA_F16(acc[mi][ni], a0, a1, a2, a3, bh[ni][0], bh[ni][1]);
                    MMA_F16(acc[mi][ni], a0, a1, a2, a3, bl[ni][0], bl[ni][1]);
                }
            }
        }
        __syncthreads();
    }

    // epilogue (acc layout: rows g, g+8; cols tg*2, tg*2+1)
    #pragma unroll
    for (int mi = 0; mi < 4; ++mi) {
        const int row0 = bm + wm + mi * 16 + g;
        #pragma unroll
        for (int ni = 0; ni < 4; ++ni) {
            const int col = bn + wn + ni * 8 + tg * 2;
            const float b0 = bias ? bias[col] : 0.0f;
            const float b1 = bias ? bias[col + 1] : 0.0f;
            float r00 = acc[mi][ni][0] * scale + b0;
            float r01 = acc[mi][ni][1] * scale + b1;
            float r10 = acc[mi][ni][2] * scale + b0;
            float r11 = acc[mi][ni][3] * scale + b1;
            if (C) {
                C[(size_t)row0 * N + col]           = r00;
                C[(size_t)row0 * N + col + 1]       = r01;
                C[(size_t)(row0 + 8) * N + col]     = r10;
                C[(size_t)(row0 + 8) * N + col + 1] = r11;
            }
            if (Oh) {
                __half h0, l0, h1, l1;
                split2h(r00, h0, l0); split2h(r01, h1, l1);
                __half2 hp = {h0, h1};
                *(__half2*)&Oh[(size_t)row0 * N + col] = hp;
                if (Ol) { __half2 lp = {l0, l1};
                          *(__half2*)&Ol[(size_t)row0 * N + col] = lp; }
                split2h(r10, h0, l0); split2h(r11, h1, l1);
                __half2 hp2 = {h0, h1};
                *(__half2*)&Oh[(size_t)(row0 + 8) * N + col] = hp2;
                if (Ol) { __half2 lp2 = {l0, l1};
                          *(__half2*)&Ol[(size_t)(row0 + 8) * N + col] = lp2; }
            }
        }
    }
}

// ---------------------------------------------------------------------------
// Row softmax (N=8192), writes fp16 hi-only attn
// ---------------------------------------------------------------------------
__global__ __launch_bounds__(256)
void softmax_half_rows(const float* __restrict__ S, __half* __restrict__ Ah)
{
    const int tid = threadIdx.x;
    const size_t rowoff = (size_t)blockIdx.x * N_ASSET;
    const float* s = S + rowoff;

    float v[32];
    float m = -3.4e38f;
    #pragma unroll
    for (int i = 0; i < 32; ++i) {
        v[i] = s[i * 256 + tid];
        m = fmaxf(m, v[i]);
    }

    __shared__ float red[8];
    __shared__ float bcast;

    #pragma unroll
    for (int o = 16; o > 0; o >>= 1) m = fmaxf(m, __shfl_xor_sync(0xffffffffu, m, o));
    if ((tid & 31) == 0) red[tid >> 5] = m;
    __syncthreads();
    if (tid < 32) {
        float t = (tid < 8) ? red[tid] : -3.4e38f;
        #pragma unroll
        for (int o = 4; o > 0; o >>= 1) t = fmaxf(t, __shfl_xor_sync(0xffffffffu, t, o));
        if (tid == 0) bcast = t;
    }
    __syncthreads();
    m = bcast;
    __syncthreads();

    float sum = 0.0f;
    #pragma unroll
    for (int i = 0; i < 32; ++i) {
        v[i] = __expf(v[i] - m);
        sum += v[i];
    }
    #pragma unroll
    for (int o = 16; o > 0; o >>= 1) sum += __shfl_xor_sync(0xffffffffu, sum, o);
    if ((tid & 31) == 0) red[tid >> 5] = sum;
    __syncthreads();
    if (tid < 32) {
        float t = (tid < 8) ? red[tid] : 0.0f;
        #pragma unroll
        for (int o = 4; o > 0; o >>= 1) t += __shfl_xor_sync(0xffffffffu, t, o);
        if (tid == 0) bcast = t;
    }
    __syncthreads();

    const float inv = 1.0f / bcast;
    #pragma unroll
    for (int i = 0; i < 32; ++i)
        Ah[rowoff + i * 256 + tid] = __float2half(v[i] * inv);
}

// ---------------------------------------------------------------------------
// kernel_launch
// ---------------------------------------------------------------------------
extern "C" void kernel_launch(void* const* d_in, const int* in_sizes, int n_in,
                              void* d_out, int out_size)
{
    const float* z  = (const float*)d_in[0];
    const float* Wq = (const float*)d_in[1];
    const float* bq = (const float*)d_in[2];
    const float* Wk = (const float*)d_in[3];
    const float* bk = (const float*)d_in[4];
    const float* Wv = (const float*)d_in[5];
    const float* bv = (const float*)d_in[6];
    float* out = (float*)d_out;

    __half *zh, *wh, *wl, *qh, *kh, *kl, *vh, *vl, *vth, *vtl, *ah;
    float *s;
    cudaGetSymbolAddress((void**)&zh, g_zh);
    cudaGetSymbolAddress((void**)&wh, g_wh);
    cudaGetSymbolAddress((void**)&wl, g_wl);
    cudaGetSymbolAddress((void**)&qh, g_qh);
    cudaGetSymbolAddress((void**)&kh, g_kh);
    cudaGetSymbolAddress((void**)&kl, g_kl);
    cudaGetSymbolAddress((void**)&vh, g_vh);
    cudaGetSymbolAddress((void**)&vl, g_vl);
    cudaGetSymbolAddress((void**)&vth, g_vth);
    cudaGetSymbolAddress((void**)&vtl, g_vtl);
    cudaGetSymbolAddress((void**)&s, g_s);
    cudaGetSymbolAddress((void**)&ah, g_ah);

    cudaFuncSetAttribute(gemm_fp16x2_nt, cudaFuncAttributeMaxDynamicSharedMemorySize, SMEM_DYN);

    const size_t zd = (size_t)N_ASSET * DLAT;
    const size_t wd = (size_t)DLAT * DLAT;

    // 1. prepare operands: z hi-only; W hi+lo
    conv_half_kernel<<<512, 256>>>(z, zh, zd);
    split_half_kernel<<<128, 256>>>(Wq, wh + 0 * wd, wl + 0 * wd, wd);
    split_half_kernel<<<128, 256>>>(Wk, wh + 1 * wd, wl + 1 * wd, wd);
    split_half_kernel<<<128, 256>>>(Wv, wh + 2 * wd, wl + 2 * wd, wd);

    // 2. QKV projections: q hi-only; k, v hi+lo
    dim3 blk(256);
    dim3 gp(DLAT / 128, N_ASSET / 128);  // 4 x 64
    gemm_fp16x2_nt<<<gp, blk, SMEM_DYN>>>(zh, wh + 0 * wd, wl + 0 * wd, bq,
                                          nullptr, qh, nullptr, N_ASSET, DLAT, DLAT, 1.0f);
    gemm_fp16x2_nt<<<gp, blk, SMEM_DYN>>>(zh, wh + 1 * wd, wl + 1 * wd, bk,
                                          nullptr, kh, kl, N_ASSET, DLAT, DLAT, 1.0f);
    gemm_fp16x2_nt<<<gp, blk, SMEM_DYN>>>(zh, wh + 2 * wd, wl + 2 * wd, bv,
                                          nullptr, vh, vl, N_ASSET, DLAT, DLAT, 1.0f);

    // 3. transpose v hi/lo -> [D][N]
    {
        dim3 tb(32, 8);
        dim3 tg(DLAT / 32, N_ASSET / 32);
        trans_half_kernel<<<tg, tb>>>(vh, vth, N_ASSET, DLAT);
        trans_half_kernel<<<tg, tb>>>(vl, vtl, N_ASSET, DLAT);
    }

    // 4. scores = q @ k^T * d^-0.5 (fp32 out); A = q (hi), B = k (hi+lo)
    dim3 gs(N_ASSET / 128, N_ASSET / 128);  // 64 x 64
    const float scale = 1.0f / sqrtf((float)DLAT);
    gemm_fp16x2_nt<<<gs, blk, SMEM_DYN>>>(qh, kh, kl, nullptr,
                                          s, nullptr, nullptr, N_ASSET, N_ASSET, DLAT, scale);

    // 5. softmax -> attn hi (fp16)
    softmax_half_rows<<<N_ASSET, blk>>>(s, ah);

    // 6. h = attn @ v : A = attn (hi), B = v^T (hi+lo), fp32 out
    dim3 gh(DLAT / 128, N_ASSET / 128);  // 4 x 64
    gemm_fp16x2_nt<<<gh, blk, SMEM_DYN>>>(ah, vth, vtl, nullptr,
                                          out, nullptr, nullptr, N_ASSET, DLAT, N_ASSET, 1.0f);
}

// round 7
// speedup vs baseline: 5.1734x; 1.4025x over previous
#include <cuda_runtime.h>
#include <cuda_fp16.h>
#include <math.h>
#include <stdint.h>

#define N_ASSET 8192
#define DLAT    512

// ---------------------------------------------------------------------------
// Scratch (__device__ globals; allocation-free rule)
// ---------------------------------------------------------------------------
__device__ __half g_zh[(size_t)N_ASSET * DLAT];
__device__ __half g_wh[3][(size_t)DLAT * DLAT];
__device__ __half g_wl[3][(size_t)DLAT * DLAT];
__device__ __half g_qh[(size_t)N_ASSET * DLAT];
__device__ __half g_kh[(size_t)N_ASSET * DLAT];
__device__ __half g_vh[(size_t)N_ASSET * DLAT];    // v hi  [N][D]
__device__ __half g_vth[(size_t)DLAT * N_ASSET];   // v^T hi [D][N]
__device__ float  g_s[(size_t)N_ASSET * N_ASSET];  // fp32 scores
__device__ __half g_ah[(size_t)N_ASSET * N_ASSET]; // attn hi

// ---------------------------------------------------------------------------
// Helpers
// ---------------------------------------------------------------------------
__device__ __forceinline__ void split2h(float x, __half& h, __half& l) {
    h = __float2half(x);
    l = __float2half(x - __half2float(h));
}

__device__ __forceinline__ uint32_t smem_u32(const void* p) {
    uint32_t a;
    asm("{ .reg .u64 t; cvta.to.shared.u64 t, %1; cvt.u32.u64 %0, t; }" : "=r"(a) : "l"(p));
    return a;
}

__device__ __forceinline__ void cp16s(uint32_t sdst, const void* src) {
    asm volatile("cp.async.cg.shared.global [%0], [%1], 16;\n" :: "r"(sdst), "l"(src));
}

#define LDSM_X4(r0, r1, r2, r3, addr) \
    asm volatile("ldmatrix.sync.aligned.m8n8.x4.shared.b16 {%0,%1,%2,%3}, [%4];" \
        : "=r"(r0), "=r"(r1), "=r"(r2), "=r"(r3) : "r"(addr))

#define MMA_F16(d, a0, a1, a2, a3, b0, b1)                                      \
    asm volatile(                                                               \
        "mma.sync.aligned.m16n8k16.row.col.f32.f16.f16.f32 "                    \
        "{%0,%1,%2,%3}, {%4,%5,%6,%7}, {%8,%9}, {%0,%1,%2,%3};\n"               \
        : "+f"(d[0]), "+f"(d[1]), "+f"(d[2]), "+f"(d[3])                        \
        : "r"(a0), "r"(a1), "r"(a2), "r"(a3), "r"(b0), "r"(b1))

// ---------------------------------------------------------------------------
// Elementwise kernels
// ---------------------------------------------------------------------------
__global__ __launch_bounds__(256)
void conv_half_kernel(const float* __restrict__ x, __half* __restrict__ h, size_t n)
{
    size_t i = (size_t)blockIdx.x * blockDim.x + threadIdx.x;
    size_t stride = (size_t)gridDim.x * blockDim.x;
    for (; i < n; i += stride) h[i] = __float2half(x[i]);
}

__global__ __launch_bounds__(256)
void split_half_kernel(const float* __restrict__ x, __half* __restrict__ h,
                       __half* __restrict__ l, size_t n)
{
    size_t i = (size_t)blockIdx.x * blockDim.x + threadIdx.x;
    size_t stride = (size_t)gridDim.x * blockDim.x;
    for (; i < n; i += stride) {
        __half hh, ll;
        split2h(x[i], hh, ll);
        h[i] = hh; l[i] = ll;
    }
}

__global__ __launch_bounds__(256)
void trans_half_kernel(const __half* __restrict__ x,
                       __half* __restrict__ y, int rows, int cols)
{
    __shared__ __half t[32][33];
    const int bx = blockIdx.x * 32;
    const int by = blockIdx.y * 32;
    const int tx = threadIdx.x, ty = threadIdx.y;

    #pragma unroll
    for (int j = 0; j < 4; ++j)
        t[ty + j * 8][tx] = x[(size_t)(by + ty + j * 8) * cols + bx + tx];
    __syncthreads();

    #pragma unroll
    for (int j = 0; j < 4; ++j)
        y[(size_t)(bx + ty + j * 8) * rows + by + tx] = t[tx][ty + j * 8];
}

// ---------------------------------------------------------------------------
// fp16 NT GEMM on tensor cores, optional 2-term B split (compile-time):
//   HASBL=1: C = scale * (A @ (Bh+Bl)^T) + bias     (3 smem tiles)
//   HASBL=0: C = scale * (A @ Bh^T) + bias          (2 smem tiles)
// Block 128x128x32, 8 warps (2x4) of 64x32, cp.async double buffer, ldmatrix.
// ---------------------------------------------------------------------------
#define GBK 32
#define ROWB 80
#define TILE_B (128 * ROWB)                  // 10240

template<bool HASBL>
__global__ __launch_bounds__(256, 2)
void gemm_f16_nt(const __half* __restrict__ Ah,
                 const __half* __restrict__ Bh, const __half* __restrict__ Bl,
                 const float* __restrict__ bias,
                 float* __restrict__ C,
                 __half* __restrict__ Oh, __half* __restrict__ Ol,
                 int M, int N, int K, float scale)
{
    constexpr int NT = HASBL ? 3 : 2;
    constexpr uint32_t STAGE_B = NT * TILE_B;

    extern __shared__ __align__(128) char dsm[];
    const uint32_t sb = smem_u32(dsm);

    const int tid = threadIdx.x, lane = tid & 31, wid = tid >> 5;
    const int bm = blockIdx.y * 128, bn = blockIdx.x * 128;
    const int wm = (wid >> 2) * 64, wn = (wid & 3) * 32;
    const int g = lane >> 2, tg = lane & 3;

    float acc[4][4][4];
    #pragma unroll
    for (int i = 0; i < 4; ++i)
        #pragma unroll
        for (int j = 0; j < 4; ++j)
            #pragma unroll
            for (int q = 0; q < 4; ++q) acc[i][j][q] = 0.0f;

    const int KT = K / GBK;

    const int lr = tid >> 2, lh = tid & 3;
    auto load_stage = [&](int kt, int s) {
        const size_t k0 = (size_t)kt * GBK;
        const uint32_t stb = sb + s * STAGE_B;
        #pragma unroll
        for (int j = 0; j < 2 * NT; ++j) {
            const int tile = j >> 1;
            const int r = ((j & 1) << 6) + lr;       // 0..127
            const __half* src =
                (tile == 0) ? Ah + (size_t)(bm + r) * K
              : (tile == 1) ? Bh + (size_t)(bn + r) * K
                            : Bl + (size_t)(bn + r) * K;
            cp16s(stb + tile * TILE_B + r * ROWB + lh * 16, src + k0 + lh * 8);
        }
    };

    load_stage(0, 0);
    asm volatile("cp.async.commit_group;\n");

    const uint32_t aRowOff = (uint32_t)(wm + (lane & 15)) * ROWB + (uint32_t)(lane >> 4) * 16;
    const uint32_t bRowOff = (uint32_t)(wn + ((lane >> 4) << 3) + (lane & 7)) * ROWB
                           + (uint32_t)((lane >> 3) & 1) * 16;

    for (int kt = 0; kt < KT; ++kt) {
        const int s = kt & 1;
        if (kt + 1 < KT) {
            load_stage(kt + 1, s ^ 1);
            asm volatile("cp.async.commit_group;\n");
            asm volatile("cp.async.wait_group 1;\n");
        } else {
            asm volatile("cp.async.wait_group 0;\n");
        }
        __syncthreads();

        const uint32_t stg = sb + s * STAGE_B;
        const uint32_t aH = stg + aRowOff;
        const uint32_t bH = stg + TILE_B + bRowOff;
        const uint32_t bL = stg + 2 * TILE_B + bRowOff;

        #pragma unroll
        for (int ks2 = 0; ks2 < 2; ++ks2) {
            const uint32_t ko = ks2 * 32;

            uint32_t bh[4][2], bl[4][2];
            #pragma unroll
            for (int p = 0; p < 2; ++p) {
                LDSM_X4(bh[2 * p][0], bh[2 * p][1], bh[2 * p + 1][0], bh[2 * p + 1][1],
                        bH + p * (16 * ROWB) + ko);
                if constexpr (HASBL) {
                    LDSM_X4(bl[2 * p][0], bl[2 * p][1], bl[2 * p + 1][0], bl[2 * p + 1][1],
                            bL + p * (16 * ROWB) + ko);
                }
            }

            #pragma unroll
            for (int mi = 0; mi < 4; ++mi) {
                uint32_t a0, a1, a2, a3;
                LDSM_X4(a0, a1, a2, a3, aH + mi * (16 * ROWB) + ko);

                #pragma unroll
                for (int ni = 0; ni < 4; ++ni) {
                    MMA_F16(acc[mi][ni], a0, a1, a2, a3, bh[ni][0], bh[ni][1]);
                    if constexpr (HASBL) {
                        MMA_F16(acc[mi][ni], a0, a1, a2, a3, bl[ni][0], bl[ni][1]);
                    }
                }
            }
        }
        __syncthreads();
    }

    // epilogue (acc layout: rows g, g+8; cols tg*2, tg*2+1)
    #pragma unroll
    for (int mi = 0; mi < 4; ++mi) {
        const int row0 = bm + wm + mi * 16 + g;
        #pragma unroll
        for (int ni = 0; ni < 4; ++ni) {
            const int col = bn + wn + ni * 8 + tg * 2;
            const float b0 = bias ? bias[col] : 0.0f;
            const float b1 = bias ? bias[col + 1] : 0.0f;
            float r00 = acc[mi][ni][0] * scale + b0;
            float r01 = acc[mi][ni][1] * scale + b1;
            float r10 = acc[mi][ni][2] * scale + b0;
            float r11 = acc[mi][ni][3] * scale + b1;
            if (C) {
                C[(size_t)row0 * N + col]           = r00;
                C[(size_t)row0 * N + col + 1]       = r01;
                C[(size_t)(row0 + 8) * N + col]     = r10;
                C[(size_t)(row0 + 8) * N + col + 1] = r11;
            }
            if (Oh) {
                __half h0, l0, h1, l1;
                split2h(r00, h0, l0); split2h(r01, h1, l1);
                __half2 hp = {h0, h1};
                *(__half2*)&Oh[(size_t)row0 * N + col] = hp;
                if (Ol) { __half2 lp = {l0, l1};
                          *(__half2*)&Ol[(size_t)row0 * N + col] = lp; }
                split2h(r10, h0, l0); split2h(r11, h1, l1);
                __half2 hp2 = {h0, h1};
                *(__half2*)&Oh[(size_t)(row0 + 8) * N + col] = hp2;
                if (Ol) { __half2 lp2 = {l0, l1};
                          *(__half2*)&Ol[(size_t)(row0 + 8) * N + col] = lp2; }
            }
        }
    }
}

// ---------------------------------------------------------------------------
// Row softmax (N=8192), writes fp16 hi-only attn
// ---------------------------------------------------------------------------
__global__ __launch_bounds__(256)
void softmax_half_rows(const float* __restrict__ S, __half* __restrict__ Ah)
{
    const int tid = threadIdx.x;
    const size_t rowoff = (size_t)blockIdx.x * N_ASSET;
    const float* s = S + rowoff;

    float v[32];
    float m = -3.4e38f;
    #pragma unroll
    for (int i = 0; i < 32; ++i) {
        v[i] = s[i * 256 + tid];
        m = fmaxf(m, v[i]);
    }

    __shared__ float red[8];
    __shared__ float bcast;

    #pragma unroll
    for (int o = 16; o > 0; o >>= 1) m = fmaxf(m, __shfl_xor_sync(0xffffffffu, m, o));
    if ((tid & 31) == 0) red[tid >> 5] = m;
    __syncthreads();
    if (tid < 32) {
        float t = (tid < 8) ? red[tid] : -3.4e38f;
        #pragma unroll
        for (int o = 4; o > 0; o >>= 1) t = fmaxf(t, __shfl_xor_sync(0xffffffffu, t, o));
        if (tid == 0) bcast = t;
    }
    __syncthreads();
    m = bcast;
    __syncthreads();

    float sum = 0.0f;
    #pragma unroll
    for (int i = 0; i < 32; ++i) {
        v[i] = __expf(v[i] - m);
        sum += v[i];
    }
    #pragma unroll
    for (int o = 16; o > 0; o >>= 1) sum += __shfl_xor_sync(0xffffffffu, sum, o);
    if ((tid & 31) == 0) red[tid >> 5] = sum;
    __syncthreads();
    if (tid < 32) {
        float t = (tid < 8) ? red[tid] : 0.0f;
        #pragma unroll
        for (int o = 4; o > 0; o >>= 1) t += __shfl_xor_sync(0xffffffffu, t, o);
        if (tid == 0) bcast = t;
    }
    __syncthreads();

    const float inv = 1.0f / bcast;
    #pragma unroll
    for (int i = 0; i < 32; ++i)
        Ah[rowoff + i * 256 + tid] = __float2half(v[i] * inv);
}

// ---------------------------------------------------------------------------
// kernel_launch
// ---------------------------------------------------------------------------
extern "C" void kernel_launch(void* const* d_in, const int* in_sizes, int n_in,
                              void* d_out, int out_size)
{
    const float* z  = (const float*)d_in[0];
    const float* Wq = (const float*)d_in[1];
    const float* bq = (const float*)d_in[2];
    const float* Wk = (const float*)d_in[3];
    const float* bk = (const float*)d_in[4];
    const float* Wv = (const float*)d_in[5];
    const float* bv = (const float*)d_in[6];
    float* out = (float*)d_out;

    __half *zh, *wh, *wl, *qh, *kh, *vh, *vth, *ah;
    float *s;
    cudaGetSymbolAddress((void**)&zh, g_zh);
    cudaGetSymbolAddress((void**)&wh, g_wh);
    cudaGetSymbolAddress((void**)&wl, g_wl);
    cudaGetSymbolAddress((void**)&qh, g_qh);
    cudaGetSymbolAddress((void**)&kh, g_kh);
    cudaGetSymbolAddress((void**)&vh, g_vh);
    cudaGetSymbolAddress((void**)&vth, g_vth);
    cudaGetSymbolAddress((void**)&s, g_s);
    cudaGetSymbolAddress((void**)&ah, g_ah);

    const int SMEM3 = 2 * 3 * TILE_B;   // 61440
    const int SMEM2 = 2 * 2 * TILE_B;   // 40960
    cudaFuncSetAttribute(gemm_f16_nt<true>,  cudaFuncAttributeMaxDynamicSharedMemorySize, SMEM3);
    cudaFuncSetAttribute(gemm_f16_nt<false>, cudaFuncAttributeMaxDynamicSharedMemorySize, SMEM2);

    const size_t zd = (size_t)N_ASSET * DLAT;
    const size_t wd = (size_t)DLAT * DLAT;

    // 1. prepare operands: z hi-only; W hi+lo
    conv_half_kernel<<<512, 256>>>(z, zh, zd);
    split_half_kernel<<<128, 256>>>(Wq, wh + 0 * wd, wl + 0 * wd, wd);
    split_half_kernel<<<128, 256>>>(Wk, wh + 1 * wd, wl + 1 * wd, wd);
    split_half_kernel<<<128, 256>>>(Wv, wh + 2 * wd, wl + 2 * wd, wd);

    // 2. QKV projections (W split, outputs hi-only fp16)
    dim3 blk(256);
    dim3 gp(DLAT / 128, N_ASSET / 128);  // 4 x 64
    gemm_f16_nt<true><<<gp, blk, SMEM3>>>(zh, wh + 0 * wd, wl + 0 * wd, bq,
                                          nullptr, qh, nullptr, N_ASSET, DLAT, DLAT, 1.0f);
    gemm_f16_nt<true><<<gp, blk, SMEM3>>>(zh, wh + 1 * wd, wl + 1 * wd, bk,
                                          nullptr, kh, nullptr, N_ASSET, DLAT, DLAT, 1.0f);
    gemm_f16_nt<true><<<gp, blk, SMEM3>>>(zh, wh + 2 * wd, wl + 2 * wd, bv,
                                          nullptr, vh, nullptr, N_ASSET, DLAT, DLAT, 1.0f);

    // 3. transpose v -> [D][N]
    {
        dim3 tb(32, 8);
        dim3 tg(DLAT / 32, N_ASSET / 32);
        trans_half_kernel<<<tg, tb>>>(vh, vth, N_ASSET, DLAT);
    }

    // 4. scores = q @ k^T * d^-0.5 (plain fp16 MMA, fp32 out)
    dim3 gs(N_ASSET / 128, N_ASSET / 128);  // 64 x 64
    const float scale = 1.0f / sqrtf((float)DLAT);
    gemm_f16_nt<false><<<gs, blk, SMEM2>>>(qh, kh, nullptr, nullptr,
                                           s, nullptr, nullptr, N_ASSET, N_ASSET, DLAT, scale);

    // 5. softmax -> attn hi (fp16)
    softmax_half_rows<<<N_ASSET, blk>>>(s, ah);

    // 6. h = attn @ v (plain fp16 MMA, fp32 out)
    dim3 gh(DLAT / 128, N_ASSET / 128);  // 4 x 64
    gemm_f16_nt<false><<<gh, blk, SMEM2>>>(ah, vth, nullptr, nullptr,
                                           out, nullptr, nullptr, N_ASSET, DLAT, N_ASSET, 1.0f);
}

// round 8
// speedup vs baseline: 5.8922x; 1.1389x over previous
#include <cuda_runtime.h>
#include <cuda_fp16.h>
#include <math.h>
#include <stdint.h>

#define N_ASSET 8192
#define DLAT    512
#define NQKV    1536   // 3 * DLAT

// ---------------------------------------------------------------------------
// Scratch (__device__ globals; allocation-free rule)
// ---------------------------------------------------------------------------
__device__ __half g_zh[(size_t)N_ASSET * DLAT];
__device__ __half g_wh[3][(size_t)DLAT * DLAT];    // contiguous: [1536][512]
__device__ __half g_wl[3][(size_t)DLAT * DLAT];
__device__ float  g_b3[NQKV];                      // concat bias
__device__ __half g_qkv[(size_t)N_ASSET * NQKV];   // q|k|v hi, ld=1536
__device__ __half g_vth[(size_t)DLAT * N_ASSET];   // v^T hi [D][N]
__device__ __half g_sh[(size_t)N_ASSET * N_ASSET]; // fp16 scores
__device__ __half g_ah[(size_t)N_ASSET * N_ASSET]; // fp16 attn

// ---------------------------------------------------------------------------
// Helpers
// ---------------------------------------------------------------------------
__device__ __forceinline__ void split2h(float x, __half& h, __half& l) {
    h = __float2half(x);
    l = __float2half(x - __half2float(h));
}

__device__ __forceinline__ uint32_t smem_u32(const void* p) {
    uint32_t a;
    asm("{ .reg .u64 t; cvta.to.shared.u64 t, %1; cvt.u32.u64 %0, t; }" : "=r"(a) : "l"(p));
    return a;
}

__device__ __forceinline__ void cp16s(uint32_t sdst, const void* src) {
    asm volatile("cp.async.cg.shared.global [%0], [%1], 16;\n" :: "r"(sdst), "l"(src));
}

#define LDSM_X4(r0, r1, r2, r3, addr) \
    asm volatile("ldmatrix.sync.aligned.m8n8.x4.shared.b16 {%0,%1,%2,%3}, [%4];" \
        : "=r"(r0), "=r"(r1), "=r"(r2), "=r"(r3) : "r"(addr))

#define MMA_F16(d, a0, a1, a2, a3, b0, b1)                                      \
    asm volatile(                                                               \
        "mma.sync.aligned.m16n8k16.row.col.f32.f16.f16.f32 "                    \
        "{%0,%1,%2,%3}, {%4,%5,%6,%7}, {%8,%9}, {%0,%1,%2,%3};\n"               \
        : "+f"(d[0]), "+f"(d[1]), "+f"(d[2]), "+f"(d[3])                        \
        : "r"(a0), "r"(a1), "r"(a2), "r"(a3), "r"(b0), "r"(b1))

// ---------------------------------------------------------------------------
// Elementwise kernels
// ---------------------------------------------------------------------------
__global__ __launch_bounds__(256)
void conv_half_kernel(const float* __restrict__ x, __half* __restrict__ h, size_t n)
{
    size_t i = (size_t)blockIdx.x * blockDim.x + threadIdx.x;
    size_t stride = (size_t)gridDim.x * blockDim.x;
    for (; i < n; i += stride) h[i] = __float2half(x[i]);
}

__global__ __launch_bounds__(256)
void split_half_kernel(const float* __restrict__ x, __half* __restrict__ h,
                       __half* __restrict__ l, size_t n)
{
    size_t i = (size_t)blockIdx.x * blockDim.x + threadIdx.x;
    size_t stride = (size_t)gridDim.x * blockDim.x;
    for (; i < n; i += stride) {
        __half hh, ll;
        split2h(x[i], hh, ll);
        h[i] = hh; l[i] = ll;
    }
}

__global__ __launch_bounds__(256)
void concat_bias_kernel(const float* __restrict__ bq, const float* __restrict__ bk,
                        const float* __restrict__ bv, float* __restrict__ b3)
{
    int i = blockIdx.x * blockDim.x + threadIdx.x;
    if (i < DLAT)            b3[i]            = bq[i];
    if (i < DLAT)            b3[i + DLAT]     = bk[i];
    if (i < DLAT)            b3[i + 2 * DLAT] = bv[i];
}

// transpose with row stride: x[rows][cols] (ld=ldx) -> y[cols][rows]
__global__ __launch_bounds__(256)
void trans_half_kernel(const __half* __restrict__ x,
                       __half* __restrict__ y, int rows, int cols, int ldx)
{
    __shared__ __half t[32][33];
    const int bx = blockIdx.x * 32;
    const int by = blockIdx.y * 32;
    const int tx = threadIdx.x, ty = threadIdx.y;

    #pragma unroll
    for (int j = 0; j < 4; ++j)
        t[ty + j * 8][tx] = x[(size_t)(by + ty + j * 8) * ldx + bx + tx];
    __syncthreads();

    #pragma unroll
    for (int j = 0; j < 4; ++j)
        y[(size_t)(bx + ty + j * 8) * rows + by + tx] = t[tx][ty + j * 8];
}

// ---------------------------------------------------------------------------
// fp16 NT GEMM, optional 2-term B split (compile-time), strided A/B:
//   HASBL=1: C/Oh = scale * (A @ (Bh+Bl)^T) + bias     (3 smem tiles/stage)
//   HASBL=0: C/Oh = scale * (A @ Bh^T) + bias          (2 smem tiles/stage)
// Block 128x128x32, 8 warps of 64x32, 3-stage cp.async, ldmatrix.
// ---------------------------------------------------------------------------
#define GBK 32
#define ROWB 80
#define TILE_B (128 * ROWB)                  // 10240
#define NSTG 3

template<bool HASBL>
__global__ __launch_bounds__(256, 2)
void gemm_f16_nt(const __half* __restrict__ Ah,
                 const __half* __restrict__ Bh, const __half* __restrict__ Bl,
                 const float* __restrict__ bias,
                 float* __restrict__ C,
                 __half* __restrict__ Oh,
                 int M, int N, int K, int lda, int ldb, float scale)
{
    constexpr int NT = HASBL ? 3 : 2;
    constexpr uint32_t STAGE_B = NT * TILE_B;

    extern __shared__ __align__(128) char dsm[];
    const uint32_t sb = smem_u32(dsm);

    const int tid = threadIdx.x, lane = tid & 31, wid = tid >> 5;
    const int bm = blockIdx.y * 128, bn = blockIdx.x * 128;
    const int wm = (wid >> 2) * 64, wn = (wid & 3) * 32;
    const int g = lane >> 2, tg = lane & 3;

    float acc[4][4][4];
    #pragma unroll
    for (int i = 0; i < 4; ++i)
        #pragma unroll
        for (int j = 0; j < 4; ++j)
            #pragma unroll
            for (int q = 0; q < 4; ++q) acc[i][j][q] = 0.0f;

    const int KT = K / GBK;

    const int lr = tid >> 2, lh = tid & 3;
    auto load_stage = [&](int kt, int s) {
        const size_t k0 = (size_t)kt * GBK;
        const uint32_t stb = sb + s * STAGE_B;
        #pragma unroll
        for (int j = 0; j < 2 * NT; ++j) {
            const int tile = j >> 1;
            const int r = ((j & 1) << 6) + lr;       // 0..127
            const __half* src =
                (tile == 0) ? Ah + (size_t)(bm + r) * lda
              : (tile == 1) ? Bh + (size_t)(bn + r) * ldb
                            : Bl + (size_t)(bn + r) * ldb;
            cp16s(stb + tile * TILE_B + r * ROWB + lh * 16, src + k0 + lh * 8);
        }
    };

    // prologue: fill all 3 stages (KT >= 3 at every call site)
    #pragma unroll
    for (int p = 0; p < NSTG; ++p) {
        load_stage(p, p);
        asm volatile("cp.async.commit_group;\n");
    }

    const uint32_t aRowOff = (uint32_t)(wm + (lane & 15)) * ROWB + (uint32_t)(lane >> 4) * 16;
    const uint32_t bRowOff = (uint32_t)(wn + ((lane >> 4) << 3) + (lane & 7)) * ROWB
                           + (uint32_t)((lane >> 3) & 1) * 16;

    for (int kt = 0; kt < KT; ++kt) {
        const int s = kt % NSTG;

        asm volatile("cp.async.wait_group 2;\n");    // stage kt resident
        __syncthreads();

        const uint32_t stg = sb + s * STAGE_B;
        const uint32_t aH = stg + aRowOff;
        const uint32_t bH = stg + TILE_B + bRowOff;
        const uint32_t bL = stg + 2 * TILE_B + bRowOff;

        #pragma unroll
        for (int ks2 = 0; ks2 < 2; ++ks2) {
            const uint32_t ko = ks2 * 32;

            uint32_t bh[4][2], bl[4][2];
            #pragma unroll
            for (int p = 0; p < 2; ++p) {
                LDSM_X4(bh[2 * p][0], bh[2 * p][1], bh[2 * p + 1][0], bh[2 * p + 1][1],
                        bH + p * (16 * ROWB) + ko);
                if constexpr (HASBL) {
                    LDSM_X4(bl[2 * p][0], bl[2 * p][1], bl[2 * p + 1][0], bl[2 * p + 1][1],
                            bL + p * (16 * ROWB) + ko);
                }
            }

            #pragma unroll
            for (int mi = 0; mi < 4; ++mi) {
                uint32_t a0, a1, a2, a3;
                LDSM_X4(a0, a1, a2, a3, aH + mi * (16 * ROWB) + ko);

                #pragma unroll
                for (int ni = 0; ni < 4; ++ni) {
                    MMA_F16(acc[mi][ni], a0, a1, a2, a3, bh[ni][0], bh[ni][1]);
                    if constexpr (HASBL) {
                        MMA_F16(acc[mi][ni], a0, a1, a2, a3, bl[ni][0], bl[ni][1]);
                    }
                }
            }
        }
        __syncthreads();                             // compute done; slot reusable

        if (kt + NSTG < KT) load_stage(kt + NSTG, s);
        asm volatile("cp.async.commit_group;\n");    // always: constant group count
    }

    // epilogue (acc layout: rows g, g+8; cols tg*2, tg*2+1)
    #pragma unroll
    for (int mi = 0; mi < 4; ++mi) {
        const int row0 = bm + wm + mi * 16 + g;
        #pragma unroll
        for (int ni = 0; ni < 4; ++ni) {
            const int col = bn + wn + ni * 8 + tg * 2;
            const float b0 = bias ? bias[col] : 0.0f;
            const float b1 = bias ? bias[col + 1] : 0.0f;
            float r00 = acc[mi][ni][0] * scale + b0;
            float r01 = acc[mi][ni][1] * scale + b1;
            float r10 = acc[mi][ni][2] * scale + b0;
            float r11 = acc[mi][ni][3] * scale + b1;
            if (C) {
                C[(size_t)row0 * N + col]           = r00;
                C[(size_t)row0 * N + col + 1]       = r01;
                C[(size_t)(row0 + 8) * N + col]     = r10;
                C[(size_t)(row0 + 8) * N + col + 1] = r11;
            }
            if (Oh) {
                __half2 hp = {__float2half(r00), __float2half(r01)};
                *(__half2*)&Oh[(size_t)row0 * N + col] = hp;
                __half2 hp2 = {__float2half(r10), __float2half(r11)};
                *(__half2*)&Oh[(size_t)(row0 + 8) * N + col] = hp2;
            }
        }
    }
}

// ---------------------------------------------------------------------------
// Row softmax (N=8192), fp16 in -> fp16 out, __half2 I/O
// Each thread owns 16 half2 (32 values): h2 index j*256 + tid.
// ---------------------------------------------------------------------------
__global__ __launch_bounds__(256)
void softmax_half_rows(const __half* __restrict__ Sh, __half* __restrict__ Ah)
{
    const int tid = threadIdx.x;
    const size_t rowoff = (size_t)blockIdx.x * N_ASSET;
    const __half2* s2 = (const __half2*)(Sh + rowoff);
    __half2* a2 = (__half2*)(Ah + rowoff);

    float vx[16], vy[16];
    float m = -3.4e38f;
    #pragma unroll
    for (int j = 0; j < 16; ++j) {
        float2 f = __half22float2(s2[j * 256 + tid]);
        vx[j] = f.x; vy[j] = f.y;
        m = fmaxf(m, fmaxf(f.x, f.y));
    }

    __shared__ float red[8];
    __shared__ float bcast;

    #pragma unroll
    for (int o = 16; o > 0; o >>= 1) m = fmaxf(m, __shfl_xor_sync(0xffffffffu, m, o));
    if ((tid & 31) == 0) red[tid >> 5] = m;
    __syncthreads();
    if (tid < 32) {
        float t = (tid < 8) ? red[tid] : -3.4e38f;
        #pragma unroll
        for (int o = 4; o > 0; o >>= 1) t = fmaxf(t, __shfl_xor_sync(0xffffffffu, t, o));
        if (tid == 0) bcast = t;
    }
    __syncthreads();
    m = bcast;
    __syncthreads();

    float sum = 0.0f;
    #pragma unroll
    for (int j = 0; j < 16; ++j) {
        vx[j] = __expf(vx[j] - m);
        vy[j] = __expf(vy[j] - m);
        sum += vx[j] + vy[j];
    }
    #pragma unroll
    for (int o = 16; o > 0; o >>= 1) sum += __shfl_xor_sync(0xffffffffu, sum, o);
    if ((tid & 31) == 0) red[tid >> 5] = sum;
    __syncthreads();
    if (tid < 32) {
        float t = (tid < 8) ? red[tid] : 0.0f;
        #pragma unroll
        for (int o = 4; o > 0; o >>= 1) t += __shfl_xor_sync(0xffffffffu, t, o);
        if (tid == 0) bcast = t;
    }
    __syncthreads();

    const float inv = 1.0f / bcast;
    #pragma unroll
    for (int j = 0; j < 16; ++j) {
        __half2 o = {__float2half(vx[j] * inv), __float2half(vy[j] * inv)};
        a2[j * 256 + tid] = o;
    }
}

// ---------------------------------------------------------------------------
// kernel_launch
// ---------------------------------------------------------------------------
extern "C" void kernel_launch(void* const* d_in, const int* in_sizes, int n_in,
                              void* d_out, int out_size)
{
    const float* z  = (const float*)d_in[0];
    const float* Wq = (const float*)d_in[1];
    const float* bq = (const float*)d_in[2];
    const float* Wk = (const float*)d_in[3];
    const float* bk = (const float*)d_in[4];
    const float* Wv = (const float*)d_in[5];
    const float* bv = (const float*)d_in[6];
    float* out = (float*)d_out;

    __half *zh, *wh, *wl, *qkv, *vth, *sh, *ah;
    float *b3;
    cudaGetSymbolAddress((void**)&zh, g_zh);
    cudaGetSymbolAddress((void**)&wh, g_wh);
    cudaGetSymbolAddress((void**)&wl, g_wl);
    cudaGetSymbolAddress((void**)&b3, g_b3);
    cudaGetSymbolAddress((void**)&qkv, g_qkv);
    cudaGetSymbolAddress((void**)&vth, g_vth);
    cudaGetSymbolAddress((void**)&sh, g_sh);
    cudaGetSymbolAddress((void**)&ah, g_ah);

    const int SMEM3 = NSTG * 3 * TILE_B;   // 92160
    const int SMEM2 = NSTG * 2 * TILE_B;   // 61440
    cudaFuncSetAttribute(gemm_f16_nt<true>,  cudaFuncAttributeMaxDynamicSharedMemorySize, SMEM3);
    cudaFuncSetAttribute(gemm_f16_nt<false>, cudaFuncAttributeMaxDynamicSharedMemorySize, SMEM2);

    const size_t zd = (size_t)N_ASSET * DLAT;
    const size_t wd = (size_t)DLAT * DLAT;

    // 1. prepare operands: z hi-only; W hi+lo; concat bias
    conv_half_kernel<<<512, 256>>>(z, zh, zd);
    split_half_kernel<<<128, 256>>>(Wq, wh + 0 * wd, wl + 0 * wd, wd);
    split_half_kernel<<<128, 256>>>(Wk, wh + 1 * wd, wl + 1 * wd, wd);
    split_half_kernel<<<128, 256>>>(Wv, wh + 2 * wd, wl + 2 * wd, wd);
    concat_bias_kernel<<<2, 256>>>(bq, bk, bv, b3);

    // 2. merged QKV projection: [8192,1536] = z @ [Wq|Wk|Wv]^T + b3 (fp16 out)
    dim3 blk(256);
    dim3 gp(NQKV / 128, N_ASSET / 128);  // 12 x 64 = 768 CTAs
    gemm_f16_nt<true><<<gp, blk, SMEM3>>>(zh, wh, wl, b3,
                                          nullptr, qkv,
                                          N_ASSET, NQKV, DLAT, DLAT, DLAT, 1.0f);

    const __half* qh = qkv;
    const __half* kh = qkv + DLAT;
    const __half* vh = qkv + 2 * DLAT;

    // 3. transpose v -> [D][N]  (v has ld=1536)
    {
        dim3 tb(32, 8);
        dim3 tg(DLAT / 32, N_ASSET / 32);
        trans_half_kernel<<<tg, tb>>>(vh, vth, N_ASSET, DLAT, NQKV);
    }

    // 4. scores = q @ k^T * d^-0.5 -> fp16
    dim3 gs(N_ASSET / 128, N_ASSET / 128);  // 64 x 64
    const float scale = 1.0f / sqrtf((float)DLAT);
    gemm_f16_nt<false><<<gs, blk, SMEM2>>>(qh, kh, nullptr, nullptr,
                                           nullptr, sh,
                                           N_ASSET, N_ASSET, DLAT, NQKV, NQKV, scale);

    // 5. softmax (fp16 -> fp16)
    softmax_half_rows<<<N_ASSET, blk>>>(sh, ah);

    // 6. h = attn @ v (fp32 out)
    dim3 gh(DLAT / 128, N_ASSET / 128);  // 4 x 64
    gemm_f16_nt<false><<<gh, blk, SMEM2>>>(ah, vth, nullptr, nullptr,
                                           out, nullptr,
                                           N_ASSET, DLAT, N_ASSET, N_ASSET, N_ASSET, 1.0f);
}